// round 11
// baseline (speedup 1.0000x reference)
#include <cuda_runtime.h>
#include <cuda_fp16.h>
#include <cstdint>
#include <math.h>

#define B_   4
#define S_   4096
#define E_   2048
#define M_   2048
#define N1   (B_ * S_)
#define DECAY_F 0.95f
#define SCALE_F 0.22360679774997896f
#define TS   256
#define NT   (S_ / TS)

// ---------------- device scratch ----------------
__device__ float g_store[(size_t)N1 * M_];   // v * sigmoid(g+bg) * scale
__device__ float g_que  [(size_t)N1 * M_];   // sigmoid(q+bq) * scale
__device__ float g_carry [B_ * NT * M_];
__device__ float g_prefix[B_ * NT * M_];
__device__ __half g_xh[(size_t)N1 * E_];
__device__ __half g_ldh[(size_t)N1 * M_];
__device__ __half g_wv[(size_t)E_ * M_];   // transposed [n][k] fp16
__device__ __half g_wg[(size_t)E_ * M_];
__device__ __half g_wq[(size_t)E_ * M_];
__device__ __half g_wo[(size_t)E_ * M_];

// ---------------- helpers ----------------
__device__ __forceinline__ uint32_t smem_u32(const void* p) {
    uint32_t a;
    asm("{ .reg .u64 t; cvta.to.shared.u64 t, %1; cvt.u32.u64 %0, t; }" : "=r"(a) : "l"(p));
    return a;
}
#define CP16(dst, src) \
    asm volatile("cp.async.cg.shared.global [%0], [%1], 16;" :: "r"(dst), "l"(src))
#define CP_COMMIT() asm volatile("cp.async.commit_group;" ::: "memory")
#define CP_WAIT(n)  asm volatile("cp.async.wait_group %0;" :: "n"(n) : "memory")

__device__ __forceinline__ void ldsm4(uint32_t* r, uint32_t addr) {
    asm volatile("ldmatrix.sync.aligned.m8n8.x4.shared.b16 {%0,%1,%2,%3}, [%4];"
        : "=r"(r[0]), "=r"(r[1]), "=r"(r[2]), "=r"(r[3]) : "r"(addr));
}
__device__ __forceinline__ void mma16816(float* d, const uint32_t* a, const uint32_t* b) {
    asm volatile(
        "mma.sync.aligned.m16n8k16.row.col.f32.f16.f16.f32 "
        "{%0,%1,%2,%3}, {%4,%5,%6,%7}, {%8,%9}, {%0,%1,%2,%3};"
        : "+f"(d[0]), "+f"(d[1]), "+f"(d[2]), "+f"(d[3])
        : "r"(a[0]), "r"(a[1]), "r"(a[2]), "r"(a[3]), "r"(b[0]), "r"(b[1]));
}
__device__ __forceinline__ float sigf(float v) { return 1.0f / (1.0f + __expf(-v)); }

#define PAD64 144   // 128B data + 16B pad: ldmatrix & cp.async conflict-free

// ---------------- conversion kernels ----------------
__global__ __launch_bounds__(256) void split_x_kernel(const float* __restrict__ x) {
    size_t i = (size_t)blockIdx.x * 256 + threadIdx.x;
    float4 v = reinterpret_cast<const float4*>(x)[i];
    reinterpret_cast<__half2*>(g_xh)[2*i] =
        __half2(__float2half(v.x), __float2half(v.y));
    reinterpret_cast<__half2*>(g_xh)[2*i+1] =
        __half2(__float2half(v.z), __float2half(v.w));
}

// W[k][n] -> T[n][k] fp16
__global__ __launch_bounds__(256) void tsplit_kernel(const float* __restrict__ W,
                                                     __half* __restrict__ Th) {
    __shared__ float tile[32][33];
    int bx = blockIdx.x * 32, by = blockIdx.y * 32;
    int tx = threadIdx.x & 31, ty = threadIdx.x >> 5;
    #pragma unroll
    for (int i = ty; i < 32; i += 8)
        tile[i][tx] = W[(size_t)(by + i) * M_ + bx + tx];
    __syncthreads();
    #pragma unroll
    for (int i = ty; i < 32; i += 8)
        Th[(size_t)(bx + i) * E_ + by + tx] = __float2half(tile[tx][i]);
}

// ---------------- gemm3: 128m x 192n (3 mats), warp 64m x 48n, BK=64 ----------------
#define ST3 ((128 + 192) * PAD64)       // 46080 B/stage
#define NKT3 (E_ / 64)                  // 32
#define FST 194                          // fp32 epilogue tile row stride (floats)
#define SM3 (3 * ST3)                    // 138240 B >= 128*194*4 = 99328 B
__global__ __launch_bounds__(256, 1) void gemm3_mma(const float* __restrict__ bg,
                                                    const float* __restrict__ bq) {
    extern __shared__ char sm[];
    uint32_t sb0 = smem_u32(sm);
    const int tid = threadIdx.x, wid = tid >> 5, lane = tid & 31;
    const int g = lane >> 2, t = lane & 3;
    const int wm = (wid & 1) * 64, wn = (wid >> 1) * 48;
    const int bn = blockIdx.x * 64, bm = blockIdx.y * 128;
    const int lrow = lane & 15;
    const int lcol = (lane >> 4) << 4;

    const __half* asrc = g_xh + (size_t)bm * E_;
    const __half* bsrc[3] = { g_wv + (size_t)bn * E_, g_wg + (size_t)bn * E_,
                              g_wq + (size_t)bn * E_ };

    float acc[4][6][4];
    #pragma unroll
    for (int i = 0; i < 4; i++)
        #pragma unroll
        for (int j = 0; j < 6; j++)
            #pragma unroll
            for (int e = 0; e < 4; e++) acc[i][j][e] = 0.f;

    auto load_stage = [&](int kt, int stg) {
        uint32_t sb = sb0 + stg * ST3;
        int k0 = kt * 64;
        #pragma unroll
        for (int j = 0; j < 10; j++) {                // 2560 CP16
            int idx = tid + j * 256;
            if (idx < 1024) {                         // A: 128 rows x 8 chunks
                int r = idx >> 3, c = idx & 7;
                CP16(sb + r * PAD64 + c * 16, asrc + (size_t)r * E_ + k0 + c * 8);
            } else {                                  // B: 192 rows x 8 chunks
                int rem = idx - 1024;
                int r = rem >> 3, c = rem & 7;
                int mat = r >> 6, nrow = r & 63;
                CP16(sb + (128 + r) * PAD64 + c * 16,
                     bsrc[mat] + (size_t)nrow * E_ + k0 + c * 8);
            }
        }
    };

    load_stage(0, 0); CP_COMMIT();
    load_stage(1, 1); CP_COMMIT();
    CP_WAIT(1);
    __syncthreads();

    for (int kt = 0; kt < NKT3; kt++) {
        int stg = kt % 3;
        uint32_t sA = sb0 + stg * ST3;
        uint32_t sB = sA + 128 * PAD64;
        uint32_t aRow = sA + (wm + lrow) * PAD64 + lcol;
        uint32_t bRow = sB + (wn + lrow) * PAD64 + lcol;

        if (kt + 2 < NKT3) load_stage(kt + 2, (kt + 2) % 3);
        CP_COMMIT();

        #pragma unroll
        for (int ks = 0; ks < 4; ks++) {
            int co = ks * 32;
            uint32_t a[4][4];
            #pragma unroll
            for (int mb = 0; mb < 4; mb++)
                ldsm4(a[mb], aRow + mb * (16 * PAD64) + co);
            #pragma unroll
            for (int p = 0; p < 3; p++) {             // nb pairs {0,1},{2,3},{4,5}
                uint32_t br[4];
                ldsm4(br, bRow + p * (16 * PAD64) + co);
                uint32_t b0[2] = { br[0], br[2] };
                uint32_t b1[2] = { br[1], br[3] };
                #pragma unroll
                for (int mb = 0; mb < 4; mb++) {
                    mma16816(acc[mb][2 * p],     a[mb], b0);
                    mma16816(acc[mb][2 * p + 1], a[mb], b1);
                }
            }
        }
        CP_WAIT(1);
        __syncthreads();
    }

    // ---- fused epilogue: stage fp32 tile in smem, re-partition, gate ----
    float* sf = reinterpret_cast<float*>(sm);
    #pragma unroll
    for (int mb = 0; mb < 4; mb++)
        #pragma unroll
        for (int nb = 0; nb < 6; nb++) {
            int c192 = wn + nb * 8 + 2 * t;
            #pragma unroll
            for (int h = 0; h < 2; h++) {
                int r = wm + mb * 16 + g + h * 8;
                *reinterpret_cast<float2*>(&sf[r * FST + c192]) =
                    make_float2(acc[mb][nb][2 * h], acc[mb][nb][2 * h + 1]);
            }
        }
    __syncthreads();

    {
        int c = tid & 63;
        int m = bn + c;
        float bgm = bg[m], bqm = bq[m];
        int r0 = tid >> 6;                            // 0..3
        #pragma unroll 8
        for (int i = 0; i < 32; i++) {
            int r = r0 + i * 4;
            float v  = sf[r * FST + c];
            float gg = sf[r * FST + 64 + c];
            float qq = sf[r * FST + 128 + c];
            size_t row = (size_t)(bm + r);
            g_store[row * M_ + m] = v * sigf(gg + bgm) * SCALE_F;
            g_que[row * M_ + m]   = sigf(qq + bqm) * SCALE_F;
        }
    }
}

// ---------------- gemm_out: 128m x 128n, warp 64m x 32n, 1-pass, BK=64, 2 CTA/SM ----------------
#define STO ((128 + 128) * PAD64)       // 36864 B/stage
#define NKTO (M_ / 64)                  // 32
__global__ __launch_bounds__(256, 2) void gemm_out_mma(float* __restrict__ out) {
    extern __shared__ char sm[];
    uint32_t sb0 = smem_u32(sm);
    const int tid = threadIdx.x, wid = tid >> 5, lane = tid & 31;
    const int g = lane >> 2, t = lane & 3;
    const int wm = (wid & 1) * 64, wn = (wid >> 1) * 32;
    const int bn = blockIdx.x * 128, bm = blockIdx.y * 128;
    const int lrow = lane & 15;
    const int lcol = (lane >> 4) << 4;

    const __half* asrc = g_ldh + (size_t)bm * M_;
    const __half* bsrc = g_wo + (size_t)bn * M_;

    float acc[4][4][4];
    #pragma unroll
    for (int i = 0; i < 4; i++)
        #pragma unroll
        for (int j = 0; j < 4; j++)
            #pragma unroll
            for (int e = 0; e < 4; e++) acc[i][j][e] = 0.f;

    auto load_stage = [&](int kt, int stg) {
        uint32_t sb = sb0 + stg * STO;
        int k0 = kt * 64;
        #pragma unroll
        for (int j = 0; j < 8; j++) {                 // 2048 CP16
            int idx = tid + j * 256;
            int half_ = idx >> 10, rem = idx & 1023, r = rem >> 3, c = rem & 7;
            const __half* src = half_ ? bsrc : asrc;
            CP16(sb + half_ * (128 * PAD64) + r * PAD64 + c * 16,
                 src + (size_t)r * M_ + k0 + c * 8);
        }
    };

    load_stage(0, 0); CP_COMMIT();

    for (int kt = 0; kt < NKTO; kt++) {
        if (kt + 1 < NKTO) {
            load_stage(kt + 1, (kt + 1) & 1);
            CP_COMMIT();
            CP_WAIT(1);
        } else {
            CP_WAIT(0);
        }
        __syncthreads();

        uint32_t sb = sb0 + (kt & 1) * STO;
        uint32_t aRow = sb + (wm + lrow) * PAD64 + lcol;
        uint32_t bRow = sb + 128 * PAD64 + (wn + lrow) * PAD64 + lcol;
        #pragma unroll
        for (int ks = 0; ks < 4; ks++) {
            int co = ks * 32;
            uint32_t a[4][4];
            #pragma unroll
            for (int mb = 0; mb < 4; mb++)
                ldsm4(a[mb], aRow + mb * (16 * PAD64) + co);
            #pragma unroll
            for (int p = 0; p < 2; p++) {
                uint32_t br[4];
                ldsm4(br, bRow + p * (16 * PAD64) + co);
                uint32_t b0[2] = { br[0], br[2] };
                uint32_t b1[2] = { br[1], br[3] };
                #pragma unroll
                for (int mb = 0; mb < 4; mb++) {
                    mma16816(acc[mb][2 * p],     a[mb], b0);
                    mma16816(acc[mb][2 * p + 1], a[mb], b1);
                }
            }
        }
        __syncthreads();
    }

    #pragma unroll
    for (int mb = 0; mb < 4; mb++)
        #pragma unroll
        for (int nb = 0; nb < 4; nb++) {
            int col = bn + wn + nb * 8 + 2 * t;
            #pragma unroll
            for (int h = 0; h < 2; h++) {
                size_t row = (size_t)(bm + wm + mb * 16 + g + h * 8);
                *reinterpret_cast<float2*>(&out[row * E_ + col]) =
                    make_float2(acc[mb][nb][2 * h], acc[mb][nb][2 * h + 1]);
            }
        }
}

// ---------------- scan kernels (float4 vectorized) ----------------
__global__ __launch_bounds__(128) void carry_kernel() {
    int m = (blockIdx.x * 128 + threadIdx.x) * 4;
    int j = blockIdx.y, b = blockIdx.z;
    size_t base = ((size_t)(b * S_ + j * TS)) * M_ + m;
    float4 c = make_float4(0.f, 0.f, 0.f, 0.f);
    #pragma unroll 4
    for (int t = 0; t < TS; t++) {
        float4 s = *reinterpret_cast<const float4*>(&g_store[base + (size_t)t * M_]);
        c.x = fmaf(DECAY_F, c.x, s.x);
        c.y = fmaf(DECAY_F, c.y, s.y);
        c.z = fmaf(DECAY_F, c.z, s.z);
        c.w = fmaf(DECAY_F, c.w, s.w);
    }
    *reinterpret_cast<float4*>(&g_carry[(size_t)(b * NT + j) * M_ + m]) = c;
}

__global__ __launch_bounds__(256) void prefix_kernel() {
    int gid = blockIdx.x * blockDim.x + threadIdx.x;   // over B_*M_/4
    int b = gid / (M_ / 4), m = (gid % (M_ / 4)) * 4;
    float aTS = DECAY_F;
    #pragma unroll
    for (int i = 0; i < 8; i++) aTS *= aTS;            // 0.95^256
    float4 run = make_float4(0.f, 0.f, 0.f, 0.f);
    #pragma unroll
    for (int j = 0; j < NT; j++) {
        size_t idx = (size_t)(b * NT + j) * M_ + m;
        *reinterpret_cast<float4*>(&g_prefix[idx]) = run;
        float4 cr = *reinterpret_cast<const float4*>(&g_carry[idx]);
        run.x = cr.x + aTS * run.x;
        run.y = cr.y + aTS * run.y;
        run.z = cr.z + aTS * run.z;
        run.w = cr.w + aTS * run.w;
    }
}

__global__ __launch_bounds__(128) void apply_kernel() {
    int m = (blockIdx.x * 128 + threadIdx.x) * 4;
    int j = blockIdx.y, b = blockIdx.z;
    size_t base = ((size_t)(b * S_ + j * TS)) * M_ + m;
    float4 c = *reinterpret_cast<const float4*>(
        &g_prefix[(size_t)(b * NT + j) * M_ + m]);
    #pragma unroll 4
    for (int t = 0; t < TS; t++) {
        size_t idx = base + (size_t)t * M_;
        float4 s = *reinterpret_cast<const float4*>(&g_store[idx]);
        float4 q = *reinterpret_cast<const float4*>(&g_que[idx]);
        c.x = fmaf(DECAY_F, c.x, s.x);
        c.y = fmaf(DECAY_F, c.y, s.y);
        c.z = fmaf(DECAY_F, c.z, s.z);
        c.w = fmaf(DECAY_F, c.w, s.w);
        __half2 h01 = __floats2half2_rn(c.x * q.x, c.y * q.y);
        __half2 h23 = __floats2half2_rn(c.z * q.z, c.w * q.w);
        __half2* dst = reinterpret_cast<__half2*>(&g_ldh[idx]);
        uint2 pk;
        pk.x = *reinterpret_cast<uint32_t*>(&h01);
        pk.y = *reinterpret_cast<uint32_t*>(&h23);
        *reinterpret_cast<uint2*>(dst) = pk;
    }
}

// ---------------- launch ----------------
extern "C" void kernel_launch(void* const* d_in, const int* in_sizes, int n_in,
                              void* d_out, int out_size) {
    const float* x  = (const float*)d_in[0];
    const float* Wv = (const float*)d_in[1];
    const float* Wg = (const float*)d_in[2];
    const float* bg = (const float*)d_in[3];
    const float* Wq = (const float*)d_in[4];
    const float* bq = (const float*)d_in[5];
    const float* Wo = (const float*)d_in[6];
    float* out = (float*)d_out;

    cudaFuncSetAttribute(gemm3_mma, cudaFuncAttributeMaxDynamicSharedMemorySize, SM3);
    cudaFuncSetAttribute(gemm_out_mma, cudaFuncAttributeMaxDynamicSharedMemorySize, 2 * STO);

    __half *wv, *wg, *wq, *wo;
    cudaGetSymbolAddress((void**)&wv, g_wv);
    cudaGetSymbolAddress((void**)&wg, g_wg);
    cudaGetSymbolAddress((void**)&wq, g_wq);
    cudaGetSymbolAddress((void**)&wo, g_wo);

    split_x_kernel<<<((size_t)N1 * E_ / 4) / 256, 256>>>(x);
    dim3 gt(M_ / 32, E_ / 32);
    tsplit_kernel<<<gt, 256>>>(Wv, wv);
    tsplit_kernel<<<gt, 256>>>(Wg, wg);
    tsplit_kernel<<<gt, 256>>>(Wq, wq);
    tsplit_kernel<<<gt, 256>>>(Wo, wo);

    gemm3_mma<<<dim3(M_ / 64, N1 / 128), 256, SM3>>>(bg, bq);

    dim3 gscan(M_ / 512, NT, B_);
    carry_kernel<<<gscan, 128>>>();
    prefix_kernel<<<(B_ * M_ / 4) / 256, 256>>>();
    apply_kernel<<<gscan, 128>>>();

    gemm_out_mma<<<dim3(E_ / 128, N1 / 128), 256, 2 * STO>>>(out);
}

// round 12
// speedup vs baseline: 1.0522x; 1.0522x over previous
#include <cuda_runtime.h>
#include <cuda_fp16.h>
#include <cstdint>
#include <math.h>

#define B_   4
#define S_   4096
#define E_   2048
#define M_   2048
#define N1   (B_ * S_)
#define DECAY_F 0.95f
#define SCALE_F 0.22360679774997896f
#define TS   128
#define NT   (S_ / TS)                  // 32

// ---------------- device scratch ----------------
__device__ float g_store[(size_t)N1 * M_];   // v * sigmoid(g+bg) * scale
__device__ float g_que  [(size_t)N1 * M_];   // sigmoid(q+bq) * scale
__device__ float g_carry [B_ * NT * M_];
__device__ float g_prefix[B_ * NT * M_];
__device__ __half g_xh[(size_t)N1 * E_];
__device__ __half g_ldh[(size_t)N1 * M_];
__device__ __half g_wv[(size_t)E_ * M_];   // transposed [n][k] fp16
__device__ __half g_wg[(size_t)E_ * M_];
__device__ __half g_wq[(size_t)E_ * M_];
__device__ __half g_wo[(size_t)E_ * M_];

// ---------------- helpers ----------------
__device__ __forceinline__ uint32_t smem_u32(const void* p) {
    uint32_t a;
    asm("{ .reg .u64 t; cvta.to.shared.u64 t, %1; cvt.u32.u64 %0, t; }" : "=r"(a) : "l"(p));
    return a;
}
#define CP16(dst, src) \
    asm volatile("cp.async.cg.shared.global [%0], [%1], 16;" :: "r"(dst), "l"(src))
#define CP_COMMIT() asm volatile("cp.async.commit_group;" ::: "memory")
#define CP_WAIT(n)  asm volatile("cp.async.wait_group %0;" :: "n"(n) : "memory")

__device__ __forceinline__ void ldsm4(uint32_t* r, uint32_t addr) {
    asm volatile("ldmatrix.sync.aligned.m8n8.x4.shared.b16 {%0,%1,%2,%3}, [%4];"
        : "=r"(r[0]), "=r"(r[1]), "=r"(r[2]), "=r"(r[3]) : "r"(addr));
}
__device__ __forceinline__ void mma16816(float* d, const uint32_t* a, const uint32_t* b) {
    asm volatile(
        "mma.sync.aligned.m16n8k16.row.col.f32.f16.f16.f32 "
        "{%0,%1,%2,%3}, {%4,%5,%6,%7}, {%8,%9}, {%0,%1,%2,%3};"
        : "+f"(d[0]), "+f"(d[1]), "+f"(d[2]), "+f"(d[3])
        : "r"(a[0]), "r"(a[1]), "r"(a[2]), "r"(a[3]), "r"(b[0]), "r"(b[1]));
}
__device__ __forceinline__ float sigf(float v) { return 1.0f / (1.0f + __expf(-v)); }

#define PAD64 144   // 128B data + 16B pad: ldmatrix & cp.async conflict-free

// ---------------- conversion kernels ----------------
__global__ __launch_bounds__(256) void split_x_kernel(const float* __restrict__ x) {
    size_t i = (size_t)blockIdx.x * 256 + threadIdx.x;
    float4 v = reinterpret_cast<const float4*>(x)[i];
    reinterpret_cast<__half2*>(g_xh)[2*i] =
        __half2(__float2half(v.x), __float2half(v.y));
    reinterpret_cast<__half2*>(g_xh)[2*i+1] =
        __half2(__float2half(v.z), __float2half(v.w));
}

// W[k][n] -> T[n][k] fp16
__global__ __launch_bounds__(256) void tsplit_kernel(const float* __restrict__ W,
                                                     __half* __restrict__ Th) {
    __shared__ float tile[32][33];
    int bx = blockIdx.x * 32, by = blockIdx.y * 32;
    int tx = threadIdx.x & 31, ty = threadIdx.x >> 5;
    #pragma unroll
    for (int i = ty; i < 32; i += 8)
        tile[i][tx] = W[(size_t)(by + i) * M_ + bx + tx];
    __syncthreads();
    #pragma unroll
    for (int i = ty; i < 32; i += 8)
        Th[(size_t)(bx + i) * E_ + by + tx] = __float2half(tile[tx][i]);
}

// ---------------- gemm3: 128m x 192n (3 mats), warp 64m x 48n, BK=64 ----------------
#define ST3 ((128 + 192) * PAD64)       // 46080 B/stage
#define NKT3 (E_ / 64)                  // 32
#define FST 194                          // fp32 epilogue tile row stride (floats)
#define SM3 (3 * ST3)                    // 138240 B >= 128*194*4 = 99328 B
__global__ __launch_bounds__(256, 1) void gemm3_mma(const float* __restrict__ bg,
                                                    const float* __restrict__ bq) {
    extern __shared__ char sm[];
    uint32_t sb0 = smem_u32(sm);
    const int tid = threadIdx.x, wid = tid >> 5, lane = tid & 31;
    const int g = lane >> 2, t = lane & 3;
    const int wm = (wid & 1) * 64, wn = (wid >> 1) * 48;
    const int bn = blockIdx.x * 64, bm = blockIdx.y * 128;
    const int lrow = lane & 15;
    const int lcol = (lane >> 4) << 4;

    const __half* asrc = g_xh + (size_t)bm * E_;
    const __half* bsrc[3] = { g_wv + (size_t)bn * E_, g_wg + (size_t)bn * E_,
                              g_wq + (size_t)bn * E_ };

    float acc[4][6][4];
    #pragma unroll
    for (int i = 0; i < 4; i++)
        #pragma unroll
        for (int j = 0; j < 6; j++)
            #pragma unroll
            for (int e = 0; e < 4; e++) acc[i][j][e] = 0.f;

    auto load_stage = [&](int kt, int stg) {
        uint32_t sb = sb0 + stg * ST3;
        int k0 = kt * 64;
        #pragma unroll
        for (int j = 0; j < 10; j++) {                // 2560 CP16
            int idx = tid + j * 256;
            if (idx < 1024) {                         // A: 128 rows x 8 chunks
                int r = idx >> 3, c = idx & 7;
                CP16(sb + r * PAD64 + c * 16, asrc + (size_t)r * E_ + k0 + c * 8);
            } else {                                  // B: 192 rows x 8 chunks
                int rem = idx - 1024;
                int r = rem >> 3, c = rem & 7;
                int mat = r >> 6, nrow = r & 63;
                CP16(sb + (128 + r) * PAD64 + c * 16,
                     bsrc[mat] + (size_t)nrow * E_ + k0 + c * 8);
            }
        }
    };

    load_stage(0, 0); CP_COMMIT();
    load_stage(1, 1); CP_COMMIT();
    CP_WAIT(1);
    __syncthreads();

    for (int kt = 0; kt < NKT3; kt++) {
        int stg = kt % 3;
        uint32_t sA = sb0 + stg * ST3;
        uint32_t sB = sA + 128 * PAD64;
        uint32_t aRow = sA + (wm + lrow) * PAD64 + lcol;
        uint32_t bRow = sB + (wn + lrow) * PAD64 + lcol;

        if (kt + 2 < NKT3) load_stage(kt + 2, (kt + 2) % 3);
        CP_COMMIT();

        #pragma unroll
        for (int ks = 0; ks < 4; ks++) {
            int co = ks * 32;
            uint32_t a[4][4];
            #pragma unroll
            for (int mb = 0; mb < 4; mb++)
                ldsm4(a[mb], aRow + mb * (16 * PAD64) + co);
            #pragma unroll
            for (int p = 0; p < 3; p++) {             // nb pairs {0,1},{2,3},{4,5}
                uint32_t br[4];
                ldsm4(br, bRow + p * (16 * PAD64) + co);
                uint32_t b0[2] = { br[0], br[2] };
                uint32_t b1[2] = { br[1], br[3] };
                #pragma unroll
                for (int mb = 0; mb < 4; mb++) {
                    mma16816(acc[mb][2 * p],     a[mb], b0);
                    mma16816(acc[mb][2 * p + 1], a[mb], b1);
                }
            }
        }
        CP_WAIT(1);
        __syncthreads();
    }

    // ---- fused epilogue: stage fp32 tile in smem, re-partition, gate,
    //      and compute the scan-tile carry (TS==128 aligns with bm tile) ----
    float* sf = reinterpret_cast<float*>(sm);
    #pragma unroll
    for (int mb = 0; mb < 4; mb++)
        #pragma unroll
        for (int nb = 0; nb < 6; nb++) {
            int c192 = wn + nb * 8 + 2 * t;
            #pragma unroll
            for (int h = 0; h < 2; h++) {
                int r = wm + mb * 16 + g + h * 8;
                *reinterpret_cast<float2*>(&sf[r * FST + c192]) =
                    make_float2(acc[mb][nb][2 * h], acc[mb][nb][2 * h + 1]);
            }
        }
    __syncthreads();

    float pc;
    int c, m;
    {
        c = tid & 63;
        m = bn + c;
        float bgm = bg[m], bqm = bq[m];
        int r0 = tid >> 6;                            // 0..3
        const float d4 = DECAY_F * DECAY_F * DECAY_F * DECAY_F;
        pc = 0.f;
        #pragma unroll 8
        for (int i = 0; i < 32; i++) {
            int r = r0 + i * 4;
            float v  = sf[r * FST + c];
            float gg = sf[r * FST + 64 + c];
            float qq = sf[r * FST + 128 + c];
            float s = v * sigf(gg + bgm) * SCALE_F;
            pc = fmaf(pc, d4, s);                     // sum s_r * d^(124-4i)
            size_t row = (size_t)(bm + r);
            g_store[row * M_ + m] = s;
            g_que[row * M_ + m]   = sigf(qq + bqm) * SCALE_F;
        }
        // exponent fix: need d^(127-r) = d^(127-r0-4i); have d^(124-4i) -> * d^(3-r0)
        #pragma unroll
        for (int k = 0; k < 3; k++)
            if (k < 3 - r0) pc *= DECAY_F;
    }
    __syncthreads();          // all tile reads done; reuse sf as scratch
    sf[tid] = pc;
    __syncthreads();
    if (tid < 64) {
        float tot = sf[tid] + sf[tid + 64] + sf[tid + 128] + sf[tid + 192];
        int b  = bm >> 12;                   // bm / S_
        int jj = (bm & (S_ - 1)) >> 7;       // scan tile of 128 rows
        g_carry[((size_t)(b * NT + jj)) * M_ + m] = tot;
    }
}

// ---------------- gemm_out: 128m x 128n, warp 64m x 32n, 1-pass, BK=64, 2 CTA/SM ----------------
#define STO ((128 + 128) * PAD64)       // 36864 B/stage
#define NKTO (M_ / 64)                  // 32
__global__ __launch_bounds__(256, 2) void gemm_out_mma(float* __restrict__ out) {
    extern __shared__ char sm[];
    uint32_t sb0 = smem_u32(sm);
    const int tid = threadIdx.x, wid = tid >> 5, lane = tid & 31;
    const int g = lane >> 2, t = lane & 3;
    const int wm = (wid & 1) * 64, wn = (wid >> 1) * 32;
    const int bn = blockIdx.x * 128, bm = blockIdx.y * 128;
    const int lrow = lane & 15;
    const int lcol = (lane >> 4) << 4;

    const __half* asrc = g_ldh + (size_t)bm * M_;
    const __half* bsrc = g_wo + (size_t)bn * M_;

    float acc[4][4][4];
    #pragma unroll
    for (int i = 0; i < 4; i++)
        #pragma unroll
        for (int j = 0; j < 4; j++)
            #pragma unroll
            for (int e = 0; e < 4; e++) acc[i][j][e] = 0.f;

    auto load_stage = [&](int kt, int stg) {
        uint32_t sb = sb0 + stg * STO;
        int k0 = kt * 64;
        #pragma unroll
        for (int j = 0; j < 8; j++) {                 // 2048 CP16
            int idx = tid + j * 256;
            int half_ = idx >> 10, rem = idx & 1023, r = rem >> 3, c = rem & 7;
            const __half* src = half_ ? bsrc : asrc;
            CP16(sb + half_ * (128 * PAD64) + r * PAD64 + c * 16,
                 src + (size_t)r * M_ + k0 + c * 8);
        }
    };

    load_stage(0, 0); CP_COMMIT();

    for (int kt = 0; kt < NKTO; kt++) {
        if (kt + 1 < NKTO) {
            load_stage(kt + 1, (kt + 1) & 1);
            CP_COMMIT();
            CP_WAIT(1);
        } else {
            CP_WAIT(0);
        }
        __syncthreads();

        uint32_t sb = sb0 + (kt & 1) * STO;
        uint32_t aRow = sb + (wm + lrow) * PAD64 + lcol;
        uint32_t bRow = sb + 128 * PAD64 + (wn + lrow) * PAD64 + lcol;
        #pragma unroll
        for (int ks = 0; ks < 4; ks++) {
            int co = ks * 32;
            uint32_t a[4][4];
            #pragma unroll
            for (int mb = 0; mb < 4; mb++)
                ldsm4(a[mb], aRow + mb * (16 * PAD64) + co);
            #pragma unroll
            for (int p = 0; p < 2; p++) {
                uint32_t br[4];
                ldsm4(br, bRow + p * (16 * PAD64) + co);
                uint32_t b0[2] = { br[0], br[2] };
                uint32_t b1[2] = { br[1], br[3] };
                #pragma unroll
                for (int mb = 0; mb < 4; mb++) {
                    mma16816(acc[mb][2 * p],     a[mb], b0);
                    mma16816(acc[mb][2 * p + 1], a[mb], b1);
                }
            }
        }
        __syncthreads();
    }

    #pragma unroll
    for (int mb = 0; mb < 4; mb++)
        #pragma unroll
        for (int nb = 0; nb < 4; nb++) {
            int col = bn + wn + nb * 8 + 2 * t;
            #pragma unroll
            for (int h = 0; h < 2; h++) {
                size_t row = (size_t)(bm + wm + mb * 16 + g + h * 8);
                *reinterpret_cast<float2*>(&out[row * E_ + col]) =
                    make_float2(acc[mb][nb][2 * h], acc[mb][nb][2 * h + 1]);
            }
        }
}

// ---------------- scan kernels (scalar, R8 form; carry now fused in gemm3) ----------------
__global__ __launch_bounds__(256) void prefix_kernel() {
    int gid = blockIdx.x * blockDim.x + threadIdx.x;
    int b = gid / M_, m = gid % M_;
    float aTS = DECAY_F;
    #pragma unroll
    for (int i = 0; i < 7; i++) aTS *= aTS;          // 0.95^128
    float run = 0.f;
    #pragma unroll
    for (int j = 0; j < NT; j++) {
        size_t idx = (size_t)(b * NT + j) * M_ + m;
        g_prefix[idx] = run;
        run = g_carry[idx] + aTS * run;
    }
}

__global__ __launch_bounds__(128) void apply_kernel() {
    int m = blockIdx.x * 128 + threadIdx.x;
    int j = blockIdx.y, b = blockIdx.z;
    size_t base = ((size_t)(b * S_ + j * TS)) * M_ + m;
    float c = g_prefix[(size_t)(b * NT + j) * M_ + m];
    #pragma unroll 4
    for (int t = 0; t < TS; t++) {
        size_t idx = base + (size_t)t * M_;
        c = fmaf(DECAY_F, c, g_store[idx]);
        g_ldh[idx] = __float2half(c * g_que[idx]);
    }
}

// ---------------- launch ----------------
extern "C" void kernel_launch(void* const* d_in, const int* in_sizes, int n_in,
                              void* d_out, int out_size) {
    const float* x  = (const float*)d_in[0];
    const float* Wv = (const float*)d_in[1];
    const float* Wg = (const float*)d_in[2];
    const float* bg = (const float*)d_in[3];
    const float* Wq = (const float*)d_in[4];
    const float* bq = (const float*)d_in[5];
    const float* Wo = (const float*)d_in[6];
    float* out = (float*)d_out;

    cudaFuncSetAttribute(gemm3_mma, cudaFuncAttributeMaxDynamicSharedMemorySize, SM3);
    cudaFuncSetAttribute(gemm_out_mma, cudaFuncAttributeMaxDynamicSharedMemorySize, 2 * STO);

    __half *wv, *wg, *wq, *wo;
    cudaGetSymbolAddress((void**)&wv, g_wv);
    cudaGetSymbolAddress((void**)&wg, g_wg);
    cudaGetSymbolAddress((void**)&wq, g_wq);
    cudaGetSymbolAddress((void**)&wo, g_wo);

    split_x_kernel<<<((size_t)N1 * E_ / 4) / 256, 256>>>(x);
    dim3 gt(M_ / 32, E_ / 32);
    tsplit_kernel<<<gt, 256>>>(Wv, wv);
    tsplit_kernel<<<gt, 256>>>(Wg, wg);
    tsplit_kernel<<<gt, 256>>>(Wq, wq);
    tsplit_kernel<<<gt, 256>>>(Wo, wo);

    gemm3_mma<<<dim3(M_ / 64, N1 / 128), 256, SM3>>>(bg, bq);

    prefix_kernel<<<(B_ * M_) / 256, 256>>>();
    dim3 gscan(M_ / 128, NT, B_);
    apply_kernel<<<gscan, 128>>>();

    gemm_out_mma<<<dim3(E_ / 128, N1 / 128), 256, 2 * STO>>>(out);
}

// round 13
// speedup vs baseline: 1.0625x; 1.0097x over previous
#include <cuda_runtime.h>
#include <cuda_fp16.h>
#include <cstdint>
#include <math.h>

#define B_   4
#define S_   4096
#define E_   2048
#define M_   2048
#define N1   (B_ * S_)
#define DECAY_F 0.95f
#define SCALE_F 0.22360679774997896f
#define TS   128
#define NT   (S_ / TS)                  // 32

// ---------------- device scratch ----------------
__device__ __half2 g_sq[(size_t)N1 * M_];    // .x = store, .y = que (both pre-scaled)
__device__ float g_carry [B_ * NT * M_];
__device__ float g_prefix[B_ * NT * M_];
__device__ __half g_xh[(size_t)N1 * E_];
__device__ __half g_ldh[(size_t)N1 * M_];
__device__ __half g_wv[(size_t)E_ * M_];   // transposed [n][k] fp16
__device__ __half g_wg[(size_t)E_ * M_];
__device__ __half g_wq[(size_t)E_ * M_];
__device__ __half g_wo[(size_t)E_ * M_];

// ---------------- helpers ----------------
__device__ __forceinline__ uint32_t smem_u32(const void* p) {
    uint32_t a;
    asm("{ .reg .u64 t; cvta.to.shared.u64 t, %1; cvt.u32.u64 %0, t; }" : "=r"(a) : "l"(p));
    return a;
}
#define CP16(dst, src) \
    asm volatile("cp.async.cg.shared.global [%0], [%1], 16;" :: "r"(dst), "l"(src))
#define CP_COMMIT() asm volatile("cp.async.commit_group;" ::: "memory")
#define CP_WAIT(n)  asm volatile("cp.async.wait_group %0;" :: "n"(n) : "memory")

__device__ __forceinline__ void ldsm4(uint32_t* r, uint32_t addr) {
    asm volatile("ldmatrix.sync.aligned.m8n8.x4.shared.b16 {%0,%1,%2,%3}, [%4];"
        : "=r"(r[0]), "=r"(r[1]), "=r"(r[2]), "=r"(r[3]) : "r"(addr));
}
__device__ __forceinline__ void mma16816(float* d, const uint32_t* a, const uint32_t* b) {
    asm volatile(
        "mma.sync.aligned.m16n8k16.row.col.f32.f16.f16.f32 "
        "{%0,%1,%2,%3}, {%4,%5,%6,%7}, {%8,%9}, {%0,%1,%2,%3};"
        : "+f"(d[0]), "+f"(d[1]), "+f"(d[2]), "+f"(d[3])
        : "r"(a[0]), "r"(a[1]), "r"(a[2]), "r"(a[3]), "r"(b[0]), "r"(b[1]));
}
__device__ __forceinline__ float sigf(float v) { return 1.0f / (1.0f + __expf(-v)); }

#define PAD64 144   // 128B data + 16B pad: ldmatrix & cp.async conflict-free

// ---------------- conversion kernels ----------------
__global__ __launch_bounds__(256) void split_x_kernel(const float* __restrict__ x) {
    size_t i = (size_t)blockIdx.x * 256 + threadIdx.x;
    float4 v = reinterpret_cast<const float4*>(x)[i];
    reinterpret_cast<__half2*>(g_xh)[2*i] =
        __half2(__float2half(v.x), __float2half(v.y));
    reinterpret_cast<__half2*>(g_xh)[2*i+1] =
        __half2(__float2half(v.z), __float2half(v.w));
}

// W[k][n] -> T[n][k] fp16
__global__ __launch_bounds__(256) void tsplit_kernel(const float* __restrict__ W,
                                                     __half* __restrict__ Th) {
    __shared__ float tile[32][33];
    int bx = blockIdx.x * 32, by = blockIdx.y * 32;
    int tx = threadIdx.x & 31, ty = threadIdx.x >> 5;
    #pragma unroll
    for (int i = ty; i < 32; i += 8)
        tile[i][tx] = W[(size_t)(by + i) * M_ + bx + tx];
    __syncthreads();
    #pragma unroll
    for (int i = ty; i < 32; i += 8)
        Th[(size_t)(bx + i) * E_ + by + tx] = __float2half(tile[tx][i]);
}

// ---------------- gemm3: 128m x 192n (3 mats), warp 64m x 48n, BK=64 ----------------
#define ST3 ((128 + 192) * PAD64)       // 46080 B/stage
#define NKT3 (E_ / 64)                  // 32
#define FST 194                          // fp32 epilogue tile row stride (floats)
#define SM3 (3 * ST3)                    // 138240 B >= 128*194*4 = 99328 B
__global__ __launch_bounds__(256, 1) void gemm3_mma(const float* __restrict__ bg,
                                                    const float* __restrict__ bq) {
    extern __shared__ char sm[];
    uint32_t sb0 = smem_u32(sm);
    const int tid = threadIdx.x, wid = tid >> 5, lane = tid & 31;
    const int g = lane >> 2, t = lane & 3;
    const int wm = (wid & 1) * 64, wn = (wid >> 1) * 48;
    const int bn = blockIdx.x * 64, bm = blockIdx.y * 128;
    const int lrow = lane & 15;
    const int lcol = (lane >> 4) << 4;

    const __half* asrc = g_xh + (size_t)bm * E_;
    const __half* bsrc[3] = { g_wv + (size_t)bn * E_, g_wg + (size_t)bn * E_,
                              g_wq + (size_t)bn * E_ };

    float acc[4][6][4];
    #pragma unroll
    for (int i = 0; i < 4; i++)
        #pragma unroll
        for (int j = 0; j < 6; j++)
            #pragma unroll
            for (int e = 0; e < 4; e++) acc[i][j][e] = 0.f;

    auto load_stage = [&](int kt, int stg) {
        uint32_t sb = sb0 + stg * ST3;
        int k0 = kt * 64;
        #pragma unroll
        for (int j = 0; j < 10; j++) {                // 2560 CP16
            int idx = tid + j * 256;
            if (idx < 1024) {                         // A: 128 rows x 8 chunks
                int r = idx >> 3, c = idx & 7;
                CP16(sb + r * PAD64 + c * 16, asrc + (size_t)r * E_ + k0 + c * 8);
            } else {                                  // B: 192 rows x 8 chunks
                int rem = idx - 1024;
                int r = rem >> 3, c = rem & 7;
                int mat = r >> 6, nrow = r & 63;
                CP16(sb + (128 + r) * PAD64 + c * 16,
                     bsrc[mat] + (size_t)nrow * E_ + k0 + c * 8);
            }
        }
    };

    load_stage(0, 0); CP_COMMIT();
    load_stage(1, 1); CP_COMMIT();
    CP_WAIT(1);
    __syncthreads();

    for (int kt = 0; kt < NKT3; kt++) {
        int stg = kt % 3;
        uint32_t sA = sb0 + stg * ST3;
        uint32_t sB = sA + 128 * PAD64;
        uint32_t aRow = sA + (wm + lrow) * PAD64 + lcol;
        uint32_t bRow = sB + (wn + lrow) * PAD64 + lcol;

        if (kt + 2 < NKT3) load_stage(kt + 2, (kt + 2) % 3);
        CP_COMMIT();

        #pragma unroll
        for (int ks = 0; ks < 4; ks++) {
            int co = ks * 32;
            uint32_t a[4][4];
            #pragma unroll
            for (int mb = 0; mb < 4; mb++)
                ldsm4(a[mb], aRow + mb * (16 * PAD64) + co);
            #pragma unroll
            for (int p = 0; p < 3; p++) {             // nb pairs {0,1},{2,3},{4,5}
                uint32_t br[4];
                ldsm4(br, bRow + p * (16 * PAD64) + co);
                uint32_t b0[2] = { br[0], br[2] };
                uint32_t b1[2] = { br[1], br[3] };
                #pragma unroll
                for (int mb = 0; mb < 4; mb++) {
                    mma16816(acc[mb][2 * p],     a[mb], b0);
                    mma16816(acc[mb][2 * p + 1], a[mb], b1);
                }
            }
        }
        CP_WAIT(1);
        __syncthreads();
    }

    // ---- fused epilogue: stage fp32 tile in smem, re-partition, gate,
    //      compute scan-tile carry (TS==128 aligns with bm tile),
    //      write packed half2 (store, que) ----
    float* sf = reinterpret_cast<float*>(sm);
    #pragma unroll
    for (int mb = 0; mb < 4; mb++)
        #pragma unroll
        for (int nb = 0; nb < 6; nb++) {
            int c192 = wn + nb * 8 + 2 * t;
            #pragma unroll
            for (int h = 0; h < 2; h++) {
                int r = wm + mb * 16 + g + h * 8;
                *reinterpret_cast<float2*>(&sf[r * FST + c192]) =
                    make_float2(acc[mb][nb][2 * h], acc[mb][nb][2 * h + 1]);
            }
        }
    __syncthreads();

    float pc;
    int c, m;
    {
        c = tid & 63;
        m = bn + c;
        float bgm = bg[m], bqm = bq[m];
        int r0 = tid >> 6;                            // 0..3
        const float d4 = DECAY_F * DECAY_F * DECAY_F * DECAY_F;
        pc = 0.f;
        #pragma unroll 8
        for (int i = 0; i < 32; i++) {
            int r = r0 + i * 4;
            float v  = sf[r * FST + c];
            float gg = sf[r * FST + 64 + c];
            float qq = sf[r * FST + 128 + c];
            float s = v * sigf(gg + bgm) * SCALE_F;
            pc = fmaf(pc, d4, s);                     // sum s_r * d^(124-4i)
            float qv = sigf(qq + bqm) * SCALE_F;
            size_t row = (size_t)(bm + r);
            g_sq[row * M_ + m] = __floats2half2_rn(s, qv);
        }
        // exponent fix: need d^(127-r) = d^(127-r0-4i); have d^(124-4i) -> * d^(3-r0)
        #pragma unroll
        for (int k = 0; k < 3; k++)
            if (k < 3 - r0) pc *= DECAY_F;
    }
    __syncthreads();          // all tile reads done; reuse sf as scratch
    sf[tid] = pc;
    __syncthreads();
    if (tid < 64) {
        float tot = sf[tid] + sf[tid + 64] + sf[tid + 128] + sf[tid + 192];
        int b  = bm >> 12;                   // bm / S_
        int jj = (bm & (S_ - 1)) >> 7;       // scan tile of 128 rows
        g_carry[((size_t)(b * NT + jj)) * M_ + m] = tot;
    }
}

// ---------------- gemm_out: 128m x 128n, warp 64m x 32n, 1-pass, BK=64, 2 CTA/SM ----------------
#define STO ((128 + 128) * PAD64)       // 36864 B/stage
#define NKTO (M_ / 64)                  // 32
__global__ __launch_bounds__(256, 2) void gemm_out_mma(float* __restrict__ out) {
    extern __shared__ char sm[];
    uint32_t sb0 = smem_u32(sm);
    const int tid = threadIdx.x, wid = tid >> 5, lane = tid & 31;
    const int g = lane >> 2, t = lane & 3;
    const int wm = (wid & 1) * 64, wn = (wid >> 1) * 32;
    const int bn = blockIdx.x * 128, bm = blockIdx.y * 128;
    const int lrow = lane & 15;
    const int lcol = (lane >> 4) << 4;

    const __half* asrc = g_ldh + (size_t)bm * M_;
    const __half* bsrc = g_wo + (size_t)bn * M_;

    float acc[4][4][4];
    #pragma unroll
    for (int i = 0; i < 4; i++)
        #pragma unroll
        for (int j = 0; j < 4; j++)
            #pragma unroll
            for (int e = 0; e < 4; e++) acc[i][j][e] = 0.f;

    auto load_stage = [&](int kt, int stg) {
        uint32_t sb = sb0 + stg * STO;
        int k0 = kt * 64;
        #pragma unroll
        for (int j = 0; j < 8; j++) {                 // 2048 CP16
            int idx = tid + j * 256;
            int half_ = idx >> 10, rem = idx & 1023, r = rem >> 3, c = rem & 7;
            const __half* src = half_ ? bsrc : asrc;
            CP16(sb + half_ * (128 * PAD64) + r * PAD64 + c * 16,
                 src + (size_t)r * M_ + k0 + c * 8);
        }
    };

    load_stage(0, 0); CP_COMMIT();

    for (int kt = 0; kt < NKTO; kt++) {
        if (kt + 1 < NKTO) {
            load_stage(kt + 1, (kt + 1) & 1);
            CP_COMMIT();
            CP_WAIT(1);
        } else {
            CP_WAIT(0);
        }
        __syncthreads();

        uint32_t sb = sb0 + (kt & 1) * STO;
        uint32_t aRow = sb + (wm + lrow) * PAD64 + lcol;
        uint32_t bRow = sb + 128 * PAD64 + (wn + lrow) * PAD64 + lcol;
        #pragma unroll
        for (int ks = 0; ks < 4; ks++) {
            int co = ks * 32;
            uint32_t a[4][4];
            #pragma unroll
            for (int mb = 0; mb < 4; mb++)
                ldsm4(a[mb], aRow + mb * (16 * PAD64) + co);
            #pragma unroll
            for (int p = 0; p < 2; p++) {
                uint32_t br[4];
                ldsm4(br, bRow + p * (16 * PAD64) + co);
                uint32_t b0[2] = { br[0], br[2] };
                uint32_t b1[2] = { br[1], br[3] };
                #pragma unroll
                for (int mb = 0; mb < 4; mb++) {
                    mma16816(acc[mb][2 * p],     a[mb], b0);
                    mma16816(acc[mb][2 * p + 1], a[mb], b1);
                }
            }
        }
        __syncthreads();
    }

    #pragma unroll
    for (int mb = 0; mb < 4; mb++)
        #pragma unroll
        for (int nb = 0; nb < 4; nb++) {
            int col = bn + wn + nb * 8 + 2 * t;
            #pragma unroll
            for (int h = 0; h < 2; h++) {
                size_t row = (size_t)(bm + wm + mb * 16 + g + h * 8);
                *reinterpret_cast<float2*>(&out[row * E_ + col]) =
                    make_float2(acc[mb][nb][2 * h], acc[mb][nb][2 * h + 1]);
            }
        }
}

// ---------------- scan kernels (carry fused in gemm3) ----------------
__global__ __launch_bounds__(256) void prefix_kernel() {
    int gid = blockIdx.x * blockDim.x + threadIdx.x;
    int b = gid / M_, m = gid % M_;
    float aTS = DECAY_F;
    #pragma unroll
    for (int i = 0; i < 7; i++) aTS *= aTS;          // 0.95^128
    float run = 0.f;
    #pragma unroll
    for (int j = 0; j < NT; j++) {
        size_t idx = (size_t)(b * NT + j) * M_ + m;
        g_prefix[idx] = run;
        run = g_carry[idx] + aTS * run;
    }
}

__global__ __launch_bounds__(128) void apply_kernel() {
    int m = blockIdx.x * 128 + threadIdx.x;
    int j = blockIdx.y, b = blockIdx.z;
    size_t base = ((size_t)(b * S_ + j * TS)) * M_ + m;
    float c = g_prefix[(size_t)(b * NT + j) * M_ + m];
    #pragma unroll 4
    for (int t = 0; t < TS; t++) {
        size_t idx = base + (size_t)t * M_;
        float2 f = __half22float2(g_sq[idx]);
        c = fmaf(DECAY_F, c, f.x);
        g_ldh[idx] = __float2half(c * f.y);
    }
}

// ---------------- launch ----------------
extern "C" void kernel_launch(void* const* d_in, const int* in_sizes, int n_in,
                              void* d_out, int out_size) {
    const float* x  = (const float*)d_in[0];
    const float* Wv = (const float*)d_in[1];
    const float* Wg = (const float*)d_in[2];
    const float* bg = (const float*)d_in[3];
    const float* Wq = (const float*)d_in[4];
    const float* bq = (const float*)d_in[5];
    const float* Wo = (const float*)d_in[6];
    float* out = (float*)d_out;

    cudaFuncSetAttribute(gemm3_mma, cudaFuncAttributeMaxDynamicSharedMemorySize, SM3);
    cudaFuncSetAttribute(gemm_out_mma, cudaFuncAttributeMaxDynamicSharedMemorySize, 2 * STO);

    __half *wv, *wg, *wq, *wo;
    cudaGetSymbolAddress((void**)&wv, g_wv);
    cudaGetSymbolAddress((void**)&wg, g_wg);
    cudaGetSymbolAddress((void**)&wq, g_wq);
    cudaGetSymbolAddress((void**)&wo, g_wo);

    split_x_kernel<<<((size_t)N1 * E_ / 4) / 256, 256>>>(x);
    dim3 gt(M_ / 32, E_ / 32);
    tsplit_kernel<<<gt, 256>>>(Wv, wv);
    tsplit_kernel<<<gt, 256>>>(Wg, wg);
    tsplit_kernel<<<gt, 256>>>(Wq, wq);
    tsplit_kernel<<<gt, 256>>>(Wo, wo);

    gemm3_mma<<<dim3(M_ / 64, N1 / 128), 256, SM3>>>(bg, bq);

    prefix_kernel<<<(B_ * M_) / 256, 256>>>();
    dim3 gscan(M_ / 128, NT, B_);
    apply_kernel<<<gscan, 128>>>();

    gemm_out_mma<<<dim3(E_ / 128, N1 / 128), 256, 2 * STO>>>(out);
}

// round 14
// speedup vs baseline: 1.1321x; 1.0656x over previous
#include <cuda_runtime.h>
#include <cuda_fp16.h>
#include <cstdint>
#include <math.h>

#define B_   4
#define S_   4096
#define E_   2048
#define M_   2048
#define N1   (B_ * S_)
#define DECAY_F 0.95f
#define SCALE_F 0.22360679774997896f
#define TS   128
#define NT   (S_ / TS)                  // 32

// ---------------- device scratch ----------------
__device__ __half2 g_sq[(size_t)N1 * M_];    // .x = store, .y = que (both pre-scaled)
__device__ float g_carry [B_ * NT * M_];
__device__ float g_prefix[B_ * NT * M_];
__device__ __half g_xh[(size_t)N1 * E_];
__device__ __half g_ldh[(size_t)N1 * M_];
__device__ __half g_wv[(size_t)E_ * M_];   // transposed [n][k] fp16
__device__ __half g_wg[(size_t)E_ * M_];
__device__ __half g_wq[(size_t)E_ * M_];
__device__ __half g_wo[(size_t)E_ * M_];

// ---------------- helpers ----------------
__device__ __forceinline__ uint32_t smem_u32(const void* p) {
    uint32_t a;
    asm("{ .reg .u64 t; cvta.to.shared.u64 t, %1; cvt.u32.u64 %0, t; }" : "=r"(a) : "l"(p));
    return a;
}
#define CP16(dst, src) \
    asm volatile("cp.async.cg.shared.global [%0], [%1], 16;" :: "r"(dst), "l"(src))
#define CP_COMMIT() asm volatile("cp.async.commit_group;" ::: "memory")
#define CP_WAIT(n)  asm volatile("cp.async.wait_group %0;" :: "n"(n) : "memory")

__device__ __forceinline__ void ldsm4(uint32_t* r, uint32_t addr) {
    asm volatile("ldmatrix.sync.aligned.m8n8.x4.shared.b16 {%0,%1,%2,%3}, [%4];"
        : "=r"(r[0]), "=r"(r[1]), "=r"(r[2]), "=r"(r[3]) : "r"(addr));
}
__device__ __forceinline__ void mma16816(float* d, const uint32_t* a, const uint32_t* b) {
    asm volatile(
        "mma.sync.aligned.m16n8k16.row.col.f32.f16.f16.f32 "
        "{%0,%1,%2,%3}, {%4,%5,%6,%7}, {%8,%9}, {%0,%1,%2,%3};"
        : "+f"(d[0]), "+f"(d[1]), "+f"(d[2]), "+f"(d[3])
        : "r"(a[0]), "r"(a[1]), "r"(a[2]), "r"(a[3]), "r"(b[0]), "r"(b[1]));
}
__device__ __forceinline__ float sigf(float v) { return 1.0f / (1.0f + __expf(-v)); }

#define PAD64 144   // 128B data + 16B pad: ldmatrix & cp.async conflict-free

// ---------------- conversion kernels ----------------
__global__ __launch_bounds__(256) void split_x_kernel(const float* __restrict__ x) {
    size_t i = (size_t)blockIdx.x * 256 + threadIdx.x;
    float4 v = reinterpret_cast<const float4*>(x)[i];
    reinterpret_cast<__half2*>(g_xh)[2*i] =
        __half2(__float2half(v.x), __float2half(v.y));
    reinterpret_cast<__half2*>(g_xh)[2*i+1] =
        __half2(__float2half(v.z), __float2half(v.w));
}

// W[k][n] -> T[n][k] fp16
__global__ __launch_bounds__(256) void tsplit_kernel(const float* __restrict__ W,
                                                     __half* __restrict__ Th) {
    __shared__ float tile[32][33];
    int bx = blockIdx.x * 32, by = blockIdx.y * 32;
    int tx = threadIdx.x & 31, ty = threadIdx.x >> 5;
    #pragma unroll
    for (int i = ty; i < 32; i += 8)
        tile[i][tx] = W[(size_t)(by + i) * M_ + bx + tx];
    __syncthreads();
    #pragma unroll
    for (int i = ty; i < 32; i += 8)
        Th[(size_t)(bx + i) * E_ + by + tx] = __float2half(tile[tx][i]);
}

// ---------------- gemm3: 128m x 192n (3 mats), 512 thr, warp 32m x 48n, BK=64 ----------------
#define ST3 ((128 + 192) * PAD64)       // 46080 B/stage
#define NKT3 (E_ / 64)                  // 32
#define FST 194                          // fp32 epilogue tile row stride (floats)
#define SM3 (3 * ST3)                    // 138240 B >= 128*194*4 = 99328 B
__global__ __launch_bounds__(512, 1) void gemm3_mma(const float* __restrict__ bg,
                                                    const float* __restrict__ bq) {
    extern __shared__ char sm[];
    uint32_t sb0 = smem_u32(sm);
    const int tid = threadIdx.x, wid = tid >> 5, lane = tid & 31;
    const int g = lane >> 2, t = lane & 3;
    const int wm = (wid & 3) * 32, wn = (wid >> 2) * 48;
    const int bn = blockIdx.x * 64, bm = blockIdx.y * 128;
    const int lrow = lane & 15;
    const int lcol = (lane >> 4) << 4;

    const __half* asrc = g_xh + (size_t)bm * E_;
    const __half* bsrc[3] = { g_wv + (size_t)bn * E_, g_wg + (size_t)bn * E_,
                              g_wq + (size_t)bn * E_ };

    float acc[2][6][4];
    #pragma unroll
    for (int i = 0; i < 2; i++)
        #pragma unroll
        for (int j = 0; j < 6; j++)
            #pragma unroll
            for (int e = 0; e < 4; e++) acc[i][j][e] = 0.f;

    auto load_stage = [&](int kt, int stg) {
        uint32_t sb = sb0 + stg * ST3;
        int k0 = kt * 64;
        #pragma unroll
        for (int j = 0; j < 5; j++) {                 // 2560 CP16
            int idx = tid + j * 512;
            if (idx < 1024) {                         // A: 128 rows x 8 chunks
                int r = idx >> 3, c = idx & 7;
                CP16(sb + r * PAD64 + c * 16, asrc + (size_t)r * E_ + k0 + c * 8);
            } else {                                  // B: 192 rows x 8 chunks
                int rem = idx - 1024;
                int r = rem >> 3, c = rem & 7;
                int mat = r >> 6, nrow = r & 63;
                CP16(sb + (128 + r) * PAD64 + c * 16,
                     bsrc[mat] + (size_t)nrow * E_ + k0 + c * 8);
            }
        }
    };

    load_stage(0, 0); CP_COMMIT();
    load_stage(1, 1); CP_COMMIT();
    CP_WAIT(1);
    __syncthreads();

    for (int kt = 0; kt < NKT3; kt++) {
        int stg = kt % 3;
        uint32_t sA = sb0 + stg * ST3;
        uint32_t sB = sA + 128 * PAD64;
        uint32_t aRow = sA + (wm + lrow) * PAD64 + lcol;
        uint32_t bRow = sB + (wn + lrow) * PAD64 + lcol;

        if (kt + 2 < NKT3) load_stage(kt + 2, (kt + 2) % 3);
        CP_COMMIT();

        #pragma unroll
        for (int ks = 0; ks < 4; ks++) {
            int co = ks * 32;
            uint32_t a[2][4];
            #pragma unroll
            for (int mb = 0; mb < 2; mb++)
                ldsm4(a[mb], aRow + mb * (16 * PAD64) + co);
            #pragma unroll
            for (int p = 0; p < 3; p++) {             // nb pairs {0,1},{2,3},{4,5}
                uint32_t br[4];
                ldsm4(br, bRow + p * (16 * PAD64) + co);
                uint32_t b0[2] = { br[0], br[2] };
                uint32_t b1[2] = { br[1], br[3] };
                #pragma unroll
                for (int mb = 0; mb < 2; mb++) {
                    mma16816(acc[mb][2 * p],     a[mb], b0);
                    mma16816(acc[mb][2 * p + 1], a[mb], b1);
                }
            }
        }
        CP_WAIT(1);
        __syncthreads();
    }

    // ---- fused epilogue: stage fp32 tile in smem, re-partition, gate,
    //      compute scan-tile carry (TS==128 aligns with bm tile),
    //      write packed half2 (store, que) ----
    float* sf = reinterpret_cast<float*>(sm);
    #pragma unroll
    for (int mb = 0; mb < 2; mb++)
        #pragma unroll
        for (int nb = 0; nb < 6; nb++) {
            int c192 = wn + nb * 8 + 2 * t;
            #pragma unroll
            for (int h = 0; h < 2; h++) {
                int r = wm + mb * 16 + g + h * 8;
                *reinterpret_cast<float2*>(&sf[r * FST + c192]) =
                    make_float2(acc[mb][nb][2 * h], acc[mb][nb][2 * h + 1]);
            }
        }
    __syncthreads();

    float pc;
    int c, m;
    {
        c = tid & 63;
        m = bn + c;
        float bgm = bg[m], bqm = bq[m];
        int r0 = tid >> 6;                            // 0..7
        float d8 = DECAY_F * DECAY_F;                 // d^2
        d8 = d8 * d8;                                 // d^4
        d8 = d8 * d8;                                 // d^8
        pc = 0.f;
        #pragma unroll 8
        for (int i = 0; i < 16; i++) {
            int r = r0 + i * 8;
            float v  = sf[r * FST + c];
            float gg = sf[r * FST + 64 + c];
            float qq = sf[r * FST + 128 + c];
            float s = v * sigf(gg + bgm) * SCALE_F;
            pc = fmaf(pc, d8, s);                     // sum s_r * d^(120-8i)
            float qv = sigf(qq + bqm) * SCALE_F;
            size_t row = (size_t)(bm + r);
            g_sq[row * M_ + m] = __floats2half2_rn(s, qv);
        }
        // exponent fix: need d^(127-r) = d^(127-r0-8i); have d^(120-8i) -> * d^(7-r0)
        #pragma unroll
        for (int k = 0; k < 7; k++)
            if (k < 7 - r0) pc *= DECAY_F;
    }
    __syncthreads();          // all tile reads done; reuse sf as scratch
    sf[tid] = pc;
    __syncthreads();
    if (tid < 64) {
        float tot = 0.f;
        #pragma unroll
        for (int k = 0; k < 8; k++) tot += sf[tid + 64 * k];
        int b  = bm >> 12;                   // bm / S_
        int jj = (bm & (S_ - 1)) >> 7;       // scan tile of 128 rows
        g_carry[((size_t)(b * NT + jj)) * M_ + m] = tot;
    }
}

// ---------------- gemm_out: 128m x 128n, warp 64m x 32n, 1-pass, BK=64, 2 CTA/SM ----------------
#define STO ((128 + 128) * PAD64)       // 36864 B/stage
#define NKTO (M_ / 64)                  // 32
__global__ __launch_bounds__(256, 2) void gemm_out_mma(float* __restrict__ out) {
    extern __shared__ char sm[];
    uint32_t sb0 = smem_u32(sm);
    const int tid = threadIdx.x, wid = tid >> 5, lane = tid & 31;
    const int g = lane >> 2, t = lane & 3;
    const int wm = (wid & 1) * 64, wn = (wid >> 1) * 32;
    const int bn = blockIdx.x * 128, bm = blockIdx.y * 128;
    const int lrow = lane & 15;
    const int lcol = (lane >> 4) << 4;

    const __half* asrc = g_ldh + (size_t)bm * M_;
    const __half* bsrc = g_wo + (size_t)bn * M_;

    float acc[4][4][4];
    #pragma unroll
    for (int i = 0; i < 4; i++)
        #pragma unroll
        for (int j = 0; j < 4; j++)
            #pragma unroll
            for (int e = 0; e < 4; e++) acc[i][j][e] = 0.f;

    auto load_stage = [&](int kt, int stg) {
        uint32_t sb = sb0 + stg * STO;
        int k0 = kt * 64;
        #pragma unroll
        for (int j = 0; j < 8; j++) {                 // 2048 CP16
            int idx = tid + j * 256;
            int half_ = idx >> 10, rem = idx & 1023, r = rem >> 3, c = rem & 7;
            const __half* src = half_ ? bsrc : asrc;
            CP16(sb + half_ * (128 * PAD64) + r * PAD64 + c * 16,
                 src + (size_t)r * M_ + k0 + c * 8);
        }
    };

    load_stage(0, 0); CP_COMMIT();

    for (int kt = 0; kt < NKTO; kt++) {
        if (kt + 1 < NKTO) {
            load_stage(kt + 1, (kt + 1) & 1);
            CP_COMMIT();
            CP_WAIT(1);
        } else {
            CP_WAIT(0);
        }
        __syncthreads();

        uint32_t sb = sb0 + (kt & 1) * STO;
        uint32_t aRow = sb + (wm + lrow) * PAD64 + lcol;
        uint32_t bRow = sb + 128 * PAD64 + (wn + lrow) * PAD64 + lcol;
        #pragma unroll
        for (int ks = 0; ks < 4; ks++) {
            int co = ks * 32;
            uint32_t a[4][4];
            #pragma unroll
            for (int mb = 0; mb < 4; mb++)
                ldsm4(a[mb], aRow + mb * (16 * PAD64) + co);
            #pragma unroll
            for (int p = 0; p < 2; p++) {
                uint32_t br[4];
                ldsm4(br, bRow + p * (16 * PAD64) + co);
                uint32_t b0[2] = { br[0], br[2] };
                uint32_t b1[2] = { br[1], br[3] };
                #pragma unroll
                for (int mb = 0; mb < 4; mb++) {
                    mma16816(acc[mb][2 * p],     a[mb], b0);
                    mma16816(acc[mb][2 * p + 1], a[mb], b1);
                }
            }
        }
        __syncthreads();
    }

    #pragma unroll
    for (int mb = 0; mb < 4; mb++)
        #pragma unroll
        for (int nb = 0; nb < 4; nb++) {
            int col = bn + wn + nb * 8 + 2 * t;
            #pragma unroll
            for (int h = 0; h < 2; h++) {
                size_t row = (size_t)(bm + wm + mb * 16 + g + h * 8);
                *reinterpret_cast<float2*>(&out[row * E_ + col]) =
                    make_float2(acc[mb][nb][2 * h], acc[mb][nb][2 * h + 1]);
            }
        }
}

// ---------------- scan kernels (carry fused in gemm3) ----------------
__global__ __launch_bounds__(256) void prefix_kernel() {
    int gid = blockIdx.x * blockDim.x + threadIdx.x;
    int b = gid / M_, m = gid % M_;
    float aTS = DECAY_F;
    #pragma unroll
    for (int i = 0; i < 7; i++) aTS *= aTS;          // 0.95^128
    float run = 0.f;
    #pragma unroll
    for (int j = 0; j < NT; j++) {
        size_t idx = (size_t)(b * NT + j) * M_ + m;
        g_prefix[idx] = run;
        run = g_carry[idx] + aTS * run;
    }
}

__global__ __launch_bounds__(128) void apply_kernel() {
    int m = blockIdx.x * 128 + threadIdx.x;
    int j = blockIdx.y, b = blockIdx.z;
    size_t base = ((size_t)(b * S_ + j * TS)) * M_ + m;
    float c = g_prefix[(size_t)(b * NT + j) * M_ + m];
    #pragma unroll 4
    for (int t = 0; t < TS; t++) {
        size_t idx = base + (size_t)t * M_;
        float2 f = __half22float2(g_sq[idx]);
        c = fmaf(DECAY_F, c, f.x);
        g_ldh[idx] = __float2half(c * f.y);
    }
}

// ---------------- launch ----------------
extern "C" void kernel_launch(void* const* d_in, const int* in_sizes, int n_in,
                              void* d_out, int out_size) {
    const float* x  = (const float*)d_in[0];
    const float* Wv = (const float*)d_in[1];
    const float* Wg = (const float*)d_in[2];
    const float* bg = (const float*)d_in[3];
    const float* Wq = (const float*)d_in[4];
    const float* bq = (const float*)d_in[5];
    const float* Wo = (const float*)d_in[6];
    float* out = (float*)d_out;

    cudaFuncSetAttribute(gemm3_mma, cudaFuncAttributeMaxDynamicSharedMemorySize, SM3);
    cudaFuncSetAttribute(gemm_out_mma, cudaFuncAttributeMaxDynamicSharedMemorySize, 2 * STO);

    __half *wv, *wg, *wq, *wo;
    cudaGetSymbolAddress((void**)&wv, g_wv);
    cudaGetSymbolAddress((void**)&wg, g_wg);
    cudaGetSymbolAddress((void**)&wq, g_wq);
    cudaGetSymbolAddress((void**)&wo, g_wo);

    split_x_kernel<<<((size_t)N1 * E_ / 4) / 256, 256>>>(x);
    dim3 gt(M_ / 32, E_ / 32);
    tsplit_kernel<<<gt, 256>>>(Wv, wv);
    tsplit_kernel<<<gt, 256>>>(Wg, wg);
    tsplit_kernel<<<gt, 256>>>(Wq, wq);
    tsplit_kernel<<<gt, 256>>>(Wo, wo);

    gemm3_mma<<<dim3(M_ / 64, N1 / 128), 512, SM3>>>(bg, bq);

    prefix_kernel<<<(B_ * M_) / 256, 256>>>();
    dim3 gscan(M_ / 128, NT, B_);
    apply_kernel<<<gscan, 128>>>();

    gemm_out_mma<<<dim3(E_ / 128, N1 / 128), 256, 2 * STO>>>(out);
}

// round 15
// speedup vs baseline: 1.1395x; 1.0065x over previous
#include <cuda_runtime.h>
#include <cuda_fp16.h>
#include <cstdint>
#include <math.h>

#define B_   4
#define S_   4096
#define E_   2048
#define M_   2048
#define N1   (B_ * S_)
#define DECAY_F 0.95f
#define SCALE_F 0.22360679774997896f
#define TS   128
#define NT   (S_ / TS)                  // 32

// ---------------- device scratch ----------------
__device__ __half2 g_sq[(size_t)N1 * M_];    // .x = store, .y = que (both pre-scaled)
__device__ float g_carry [B_ * NT * M_];
__device__ float g_prefix[B_ * NT * M_];
__device__ __half g_xh[(size_t)N1 * E_];
__device__ __half g_ldh[(size_t)N1 * M_];
__device__ __half g_wv[(size_t)E_ * M_];   // transposed [n][k] fp16
__device__ __half g_wg[(size_t)E_ * M_];
__device__ __half g_wq[(size_t)E_ * M_];
__device__ __half g_wo[(size_t)E_ * M_];

// ---------------- helpers ----------------
__device__ __forceinline__ uint32_t smem_u32(const void* p) {
    uint32_t a;
    asm("{ .reg .u64 t; cvta.to.shared.u64 t, %1; cvt.u32.u64 %0, t; }" : "=r"(a) : "l"(p));
    return a;
}
#define CP16(dst, src) \
    asm volatile("cp.async.cg.shared.global [%0], [%1], 16;" :: "r"(dst), "l"(src))
#define CP_COMMIT() asm volatile("cp.async.commit_group;" ::: "memory")
#define CP_WAIT(n)  asm volatile("cp.async.wait_group %0;" :: "n"(n) : "memory")

__device__ __forceinline__ void ldsm4(uint32_t* r, uint32_t addr) {
    asm volatile("ldmatrix.sync.aligned.m8n8.x4.shared.b16 {%0,%1,%2,%3}, [%4];"
        : "=r"(r[0]), "=r"(r[1]), "=r"(r[2]), "=r"(r[3]) : "r"(addr));
}
__device__ __forceinline__ void mma16816(float* d, const uint32_t* a, const uint32_t* b) {
    asm volatile(
        "mma.sync.aligned.m16n8k16.row.col.f32.f16.f16.f32 "
        "{%0,%1,%2,%3}, {%4,%5,%6,%7}, {%8,%9}, {%0,%1,%2,%3};"
        : "+f"(d[0]), "+f"(d[1]), "+f"(d[2]), "+f"(d[3])
        : "r"(a[0]), "r"(a[1]), "r"(a[2]), "r"(a[3]), "r"(b[0]), "r"(b[1]));
}
__device__ __forceinline__ float sigf(float v) { return 1.0f / (1.0f + __expf(-v)); }

#define PAD64 144   // 128B data + 16B pad: ldmatrix & cp.async conflict-free

// ---------------- conversion kernels ----------------
__global__ __launch_bounds__(256) void split_x_kernel(const float* __restrict__ x) {
    size_t i0 = (size_t)blockIdx.x * 512 + threadIdx.x;
    #pragma unroll
    for (int u = 0; u < 2; u++) {
        size_t i = i0 + u * 256;
        float4 v = reinterpret_cast<const float4*>(x)[i];
        reinterpret_cast<__half2*>(g_xh)[2*i] =
            __half2(__float2half(v.x), __float2half(v.y));
        reinterpret_cast<__half2*>(g_xh)[2*i+1] =
            __half2(__float2half(v.z), __float2half(v.w));
    }
}

// all 4 weights in ONE launch: blockIdx.z selects matrix. W[k][n] -> T[n][k] fp16
__global__ __launch_bounds__(256) void tsplit_kernel(const float* __restrict__ W0,
                                                     const float* __restrict__ W1,
                                                     const float* __restrict__ W2,
                                                     const float* __restrict__ W3,
                                                     __half* __restrict__ T0,
                                                     __half* __restrict__ T1,
                                                     __half* __restrict__ T2,
                                                     __half* __restrict__ T3) {
    __shared__ float tile[32][33];
    const float* W = (blockIdx.z == 0) ? W0 : (blockIdx.z == 1) ? W1
                   : (blockIdx.z == 2) ? W2 : W3;
    __half* Th = (blockIdx.z == 0) ? T0 : (blockIdx.z == 1) ? T1
               : (blockIdx.z == 2) ? T2 : T3;
    int bx = blockIdx.x * 32, by = blockIdx.y * 32;
    int tx = threadIdx.x & 31, ty = threadIdx.x >> 5;
    #pragma unroll
    for (int i = ty; i < 32; i += 8)
        tile[i][tx] = W[(size_t)(by + i) * M_ + bx + tx];
    __syncthreads();
    #pragma unroll
    for (int i = ty; i < 32; i += 8)
        Th[(size_t)(bx + i) * E_ + by + tx] = __float2half(tile[tx][i]);
}

// ---------------- gemm3: 128m x 192n (3 mats), 512 thr, warp 32m x 48n, BK=64 ----------------
#define ST3 ((128 + 192) * PAD64)       // 46080 B/stage
#define NKT3 (E_ / 64)                  // 32
#define FST 194                          // fp32 epilogue tile row stride (floats)
#define SM3 (3 * ST3)                    // 138240 B >= 128*194*4 = 99328 B
__global__ __launch_bounds__(512, 1) void gemm3_mma(const float* __restrict__ bg,
                                                    const float* __restrict__ bq) {
    extern __shared__ char sm[];
    uint32_t sb0 = smem_u32(sm);
    const int tid = threadIdx.x, wid = tid >> 5, lane = tid & 31;
    const int g = lane >> 2, t = lane & 3;
    const int wm = (wid & 3) * 32, wn = (wid >> 2) * 48;
    const int bn = blockIdx.x * 64, bm = blockIdx.y * 128;
    const int lrow = lane & 15;
    const int lcol = (lane >> 4) << 4;

    const __half* asrc = g_xh + (size_t)bm * E_;
    const __half* bsrc[3] = { g_wv + (size_t)bn * E_, g_wg + (size_t)bn * E_,
                              g_wq + (size_t)bn * E_ };

    float acc[2][6][4];
    #pragma unroll
    for (int i = 0; i < 2; i++)
        #pragma unroll
        for (int j = 0; j < 6; j++)
            #pragma unroll
            for (int e = 0; e < 4; e++) acc[i][j][e] = 0.f;

    auto load_stage = [&](int kt, int stg) {
        uint32_t sb = sb0 + stg * ST3;
        int k0 = kt * 64;
        #pragma unroll
        for (int j = 0; j < 5; j++) {                 // 2560 CP16
            int idx = tid + j * 512;
            if (idx < 1024) {                         // A: 128 rows x 8 chunks
                int r = idx >> 3, c = idx & 7;
                CP16(sb + r * PAD64 + c * 16, asrc + (size_t)r * E_ + k0 + c * 8);
            } else {                                  // B: 192 rows x 8 chunks
                int rem = idx - 1024;
                int r = rem >> 3, c = rem & 7;
                int mat = r >> 6, nrow = r & 63;
                CP16(sb + (128 + r) * PAD64 + c * 16,
                     bsrc[mat] + (size_t)nrow * E_ + k0 + c * 8);
            }
        }
    };

    load_stage(0, 0); CP_COMMIT();
    load_stage(1, 1); CP_COMMIT();
    CP_WAIT(1);
    __syncthreads();

    for (int kt = 0; kt < NKT3; kt++) {
        int stg = kt % 3;
        uint32_t sA = sb0 + stg * ST3;
        uint32_t sB = sA + 128 * PAD64;
        uint32_t aRow = sA + (wm + lrow) * PAD64 + lcol;
        uint32_t bRow = sB + (wn + lrow) * PAD64 + lcol;

        if (kt + 2 < NKT3) load_stage(kt + 2, (kt + 2) % 3);
        CP_COMMIT();

        #pragma unroll
        for (int ks = 0; ks < 4; ks++) {
            int co = ks * 32;
            uint32_t a[2][4];
            #pragma unroll
            for (int mb = 0; mb < 2; mb++)
                ldsm4(a[mb], aRow + mb * (16 * PAD64) + co);
            #pragma unroll
            for (int p = 0; p < 3; p++) {             // nb pairs {0,1},{2,3},{4,5}
                uint32_t br[4];
                ldsm4(br, bRow + p * (16 * PAD64) + co);
                uint32_t b0[2] = { br[0], br[2] };
                uint32_t b1[2] = { br[1], br[3] };
                #pragma unroll
                for (int mb = 0; mb < 2; mb++) {
                    mma16816(acc[mb][2 * p],     a[mb], b0);
                    mma16816(acc[mb][2 * p + 1], a[mb], b1);
                }
            }
        }
        CP_WAIT(1);
        __syncthreads();
    }

    // ---- fused epilogue: stage fp32 tile in smem, re-partition, gate,
    //      compute scan-tile carry (TS==128 aligns with bm tile),
    //      write packed half2 (store, que) ----
    float* sf = reinterpret_cast<float*>(sm);
    #pragma unroll
    for (int mb = 0; mb < 2; mb++)
        #pragma unroll
        for (int nb = 0; nb < 6; nb++) {
            int c192 = wn + nb * 8 + 2 * t;
            #pragma unroll
            for (int h = 0; h < 2; h++) {
                int r = wm + mb * 16 + g + h * 8;
                *reinterpret_cast<float2*>(&sf[r * FST + c192]) =
                    make_float2(acc[mb][nb][2 * h], acc[mb][nb][2 * h + 1]);
            }
        }
    __syncthreads();

    float pc;
    int c, m;
    {
        c = tid & 63;
        m = bn + c;
        float bgm = bg[m], bqm = bq[m];
        int r0 = tid >> 6;                            // 0..7
        float d8 = DECAY_F * DECAY_F;                 // d^2
        d8 = d8 * d8;                                 // d^4
        d8 = d8 * d8;                                 // d^8
        pc = 0.f;
        #pragma unroll 8
        for (int i = 0; i < 16; i++) {
            int r = r0 + i * 8;
            float v  = sf[r * FST + c];
            float gg = sf[r * FST + 64 + c];
            float qq = sf[r * FST + 128 + c];
            float s = v * sigf(gg + bgm) * SCALE_F;
            pc = fmaf(pc, d8, s);                     // sum s_r * d^(120-8i)
            float qv = sigf(qq + bqm) * SCALE_F;
            size_t row = (size_t)(bm + r);
            g_sq[row * M_ + m] = __floats2half2_rn(s, qv);
        }
        // exponent fix: need d^(127-r) = d^(127-r0-8i); have d^(120-8i) -> * d^(7-r0)
        #pragma unroll
        for (int k = 0; k < 7; k++)
            if (k < 7 - r0) pc *= DECAY_F;
    }
    __syncthreads();          // all tile reads done; reuse sf as scratch
    sf[tid] = pc;
    __syncthreads();
    if (tid < 64) {
        float tot = 0.f;
        #pragma unroll
        for (int k = 0; k < 8; k++) tot += sf[tid + 64 * k];
        int b  = bm >> 12;                   // bm / S_
        int jj = (bm & (S_ - 1)) >> 7;       // scan tile of 128 rows
        g_carry[((size_t)(b * NT + jj)) * M_ + m] = tot;
    }
}

// ---------------- gemm_out: 128m x 128n, warp 64m x 32n, 1-pass, BK=64, 2 CTA/SM ----------------
#define STO ((128 + 128) * PAD64)       // 36864 B/stage
#define NKTO (M_ / 64)                  // 32
__global__ __launch_bounds__(256, 2) void gemm_out_mma(float* __restrict__ out) {
    extern __shared__ char sm[];
    uint32_t sb0 = smem_u32(sm);
    const int tid = threadIdx.x, wid = tid >> 5, lane = tid & 31;
    const int g = lane >> 2, t = lane & 3;
    const int wm = (wid & 1) * 64, wn = (wid >> 1) * 32;
    const int bn = blockIdx.x * 128, bm = blockIdx.y * 128;
    const int lrow = lane & 15;
    const int lcol = (lane >> 4) << 4;

    const __half* asrc = g_ldh + (size_t)bm * M_;
    const __half* bsrc = g_wo + (size_t)bn * M_;

    float acc[4][4][4];
    #pragma unroll
    for (int i = 0; i < 4; i++)
        #pragma unroll
        for (int j = 0; j < 4; j++)
            #pragma unroll
            for (int e = 0; e < 4; e++) acc[i][j][e] = 0.f;

    auto load_stage = [&](int kt, int stg) {
        uint32_t sb = sb0 + stg * STO;
        int k0 = kt * 64;
        #pragma unroll
        for (int j = 0; j < 8; j++) {                 // 2048 CP16
            int idx = tid + j * 256;
            int half_ = idx >> 10, rem = idx & 1023, r = rem >> 3, c = rem & 7;
            const __half* src = half_ ? bsrc : asrc;
            CP16(sb + half_ * (128 * PAD64) + r * PAD64 + c * 16,
                 src + (size_t)r * M_ + k0 + c * 8);
        }
    };

    load_stage(0, 0); CP_COMMIT();

    for (int kt = 0; kt < NKTO; kt++) {
        if (kt + 1 < NKTO) {
            load_stage(kt + 1, (kt + 1) & 1);
            CP_COMMIT();
            CP_WAIT(1);
        } else {
            CP_WAIT(0);
        }
        __syncthreads();

        uint32_t sb = sb0 + (kt & 1) * STO;
        uint32_t aRow = sb + (wm + lrow) * PAD64 + lcol;
        uint32_t bRow = sb + 128 * PAD64 + (wn + lrow) * PAD64 + lcol;
        #pragma unroll
        for (int ks = 0; ks < 4; ks++) {
            int co = ks * 32;
            uint32_t a[4][4];
            #pragma unroll
            for (int mb = 0; mb < 4; mb++)
                ldsm4(a[mb], aRow + mb * (16 * PAD64) + co);
            #pragma unroll
            for (int p = 0; p < 2; p++) {
                uint32_t br[4];
                ldsm4(br, bRow + p * (16 * PAD64) + co);
                uint32_t b0[2] = { br[0], br[2] };
                uint32_t b1[2] = { br[1], br[3] };
                #pragma unroll
                for (int mb = 0; mb < 4; mb++) {
                    mma16816(acc[mb][2 * p],     a[mb], b0);
                    mma16816(acc[mb][2 * p + 1], a[mb], b1);
                }
            }
        }
        __syncthreads();
    }

    #pragma unroll
    for (int mb = 0; mb < 4; mb++)
        #pragma unroll
        for (int nb = 0; nb < 4; nb++) {
            int col = bn + wn + nb * 8 + 2 * t;
            #pragma unroll
            for (int h = 0; h < 2; h++) {
                size_t row = (size_t)(bm + wm + mb * 16 + g + h * 8);
                *reinterpret_cast<float2*>(&out[row * E_ + col]) =
                    make_float2(acc[mb][nb][2 * h], acc[mb][nb][2 * h + 1]);
            }
        }
}

// ---------------- scan kernels (carry fused in gemm3) ----------------
__global__ __launch_bounds__(256) void prefix_kernel() {
    int gid = blockIdx.x * blockDim.x + threadIdx.x;
    int b = gid / M_, m = gid % M_;
    float aTS = DECAY_F;
    #pragma unroll
    for (int i = 0; i < 7; i++) aTS *= aTS;          // 0.95^128
    float run = 0.f;
    #pragma unroll
    for (int j = 0; j < NT; j++) {
        size_t idx = (size_t)(b * NT + j) * M_ + m;
        g_prefix[idx] = run;
        run = g_carry[idx] + aTS * run;
    }
}

__global__ __launch_bounds__(128) void apply_kernel() {
    int m = blockIdx.x * 128 + threadIdx.x;
    int j = blockIdx.y, b = blockIdx.z;
    size_t base = ((size_t)(b * S_ + j * TS)) * M_ + m;
    float c = g_prefix[(size_t)(b * NT + j) * M_ + m];
    #pragma unroll 8
    for (int t = 0; t < TS; t++) {
        size_t idx = base + (size_t)t * M_;
        float2 f = __half22float2(g_sq[idx]);
        c = fmaf(DECAY_F, c, f.x);
        g_ldh[idx] = __float2half(c * f.y);
    }
}

// ---------------- launch ----------------
extern "C" void kernel_launch(void* const* d_in, const int* in_sizes, int n_in,
                              void* d_out, int out_size) {
    const float* x  = (const float*)d_in[0];
    const float* Wv = (const float*)d_in[1];
    const float* Wg = (const float*)d_in[2];
    const float* bg = (const float*)d_in[3];
    const float* Wq = (const float*)d_in[4];
    const float* bq = (const float*)d_in[5];
    const float* Wo = (const float*)d_in[6];
    float* out = (float*)d_out;

    cudaFuncSetAttribute(gemm3_mma, cudaFuncAttributeMaxDynamicSharedMemorySize, SM3);
    cudaFuncSetAttribute(gemm_out_mma, cudaFuncAttributeMaxDynamicSharedMemorySize, 2 * STO);

    __half *wv, *wg, *wq, *wo;
    cudaGetSymbolAddress((void**)&wv, g_wv);
    cudaGetSymbolAddress((void**)&wg, g_wg);
    cudaGetSymbolAddress((void**)&wq, g_wq);
    cudaGetSymbolAddress((void**)&wo, g_wo);

    split_x_kernel<<<((size_t)N1 * E_ / 4) / 512, 256>>>(x);
    dim3 gt(M_ / 32, E_ / 32, 4);
    tsplit_kernel<<<gt, 256>>>(Wv, Wg, Wq, Wo, wv, wg, wq, wo);

    gemm3_mma<<<dim3(M_ / 64, N1 / 128), 512, SM3>>>(bg, bq);

    prefix_kernel<<<(B_ * M_) / 256, 256>>>();
    dim3 gscan(M_ / 128, NT, B_);
    apply_kernel<<<gscan, 128>>>();

    gemm_out_mma<<<dim3(E_ / 128, N1 / 128), 256, 2 * STO>>>(out);
}

// round 16
// speedup vs baseline: 1.1494x; 1.0087x over previous
#include <cuda_runtime.h>
#include <cuda_fp16.h>
#include <cstdint>
#include <math.h>

#define B_   4
#define S_   4096
#define E_   2048
#define M_   2048
#define N1   (B_ * S_)
#define DECAY_F 0.95f
#define SCALE_F 0.22360679774997896f
#define TS   128
#define NT   (S_ / TS)                  // 32

// ---------------- device scratch ----------------
__device__ __half2 g_sq[(size_t)N1 * M_];    // .x = store, .y = que (both pre-scaled)
__device__ float g_carry [B_ * NT * M_];
__device__ __half g_xh[(size_t)N1 * E_];
__device__ __half g_ldh[(size_t)N1 * M_];
__device__ __half g_wv[(size_t)E_ * M_];   // transposed [n][k] fp16
__device__ __half g_wg[(size_t)E_ * M_];
__device__ __half g_wq[(size_t)E_ * M_];
__device__ __half g_wo[(size_t)E_ * M_];

// ---------------- helpers ----------------
__device__ __forceinline__ uint32_t smem_u32(const void* p) {
    uint32_t a;
    asm("{ .reg .u64 t; cvta.to.shared.u64 t, %1; cvt.u32.u64 %0, t; }" : "=r"(a) : "l"(p));
    return a;
}
#define CP16(dst, src) \
    asm volatile("cp.async.cg.shared.global [%0], [%1], 16;" :: "r"(dst), "l"(src))
#define CP_COMMIT() asm volatile("cp.async.commit_group;" ::: "memory")
#define CP_WAIT(n)  asm volatile("cp.async.wait_group %0;" :: "n"(n) : "memory")

__device__ __forceinline__ void ldsm4(uint32_t* r, uint32_t addr) {
    asm volatile("ldmatrix.sync.aligned.m8n8.x4.shared.b16 {%0,%1,%2,%3}, [%4];"
        : "=r"(r[0]), "=r"(r[1]), "=r"(r[2]), "=r"(r[3]) : "r"(addr));
}
__device__ __forceinline__ void mma16816(float* d, const uint32_t* a, const uint32_t* b) {
    asm volatile(
        "mma.sync.aligned.m16n8k16.row.col.f32.f16.f16.f32 "
        "{%0,%1,%2,%3}, {%4,%5,%6,%7}, {%8,%9}, {%0,%1,%2,%3};"
        : "+f"(d[0]), "+f"(d[1]), "+f"(d[2]), "+f"(d[3])
        : "r"(a[0]), "r"(a[1]), "r"(a[2]), "r"(a[3]), "r"(b[0]), "r"(b[1]));
}
__device__ __forceinline__ float sigf(float v) { return 1.0f / (1.0f + __expf(-v)); }

#define PAD64 144   // 128B data + 16B pad: ldmatrix & cp.async conflict-free

// ---------------- fused prep: weight transposes + x conversion, ONE launch ----------------
// blocks [0, 16384): tsplit (4 mats x 64 x 64 tiles); blocks [16384, 32768): split_x
#define NPREP_W 16384
__global__ __launch_bounds__(256) void prep_kernel(const float* __restrict__ x,
                                                   const float* __restrict__ W0,
                                                   const float* __restrict__ W1,
                                                   const float* __restrict__ W2,
                                                   const float* __restrict__ W3,
                                                   __half* __restrict__ T0,
                                                   __half* __restrict__ T1,
                                                   __half* __restrict__ T2,
                                                   __half* __restrict__ T3) {
    int bid = blockIdx.x;
    if (bid < NPREP_W) {
        __shared__ float tile[32][33];
        int mat = bid >> 12, rem = bid & 4095;
        const float* W = (mat == 0) ? W0 : (mat == 1) ? W1 : (mat == 2) ? W2 : W3;
        __half* Th = (mat == 0) ? T0 : (mat == 1) ? T1 : (mat == 2) ? T2 : T3;
        int bx = (rem & 63) * 32, by = (rem >> 6) * 32;
        int tx = threadIdx.x & 31, ty = threadIdx.x >> 5;
        #pragma unroll
        for (int i = ty; i < 32; i += 8)
            tile[i][tx] = W[(size_t)(by + i) * M_ + bx + tx];
        __syncthreads();
        #pragma unroll
        for (int i = ty; i < 32; i += 8)
            Th[(size_t)(bx + i) * E_ + by + tx] = __float2half(tile[tx][i]);
    } else {
        size_t i0 = (size_t)(bid - NPREP_W) * 512 + threadIdx.x;
        #pragma unroll
        for (int u = 0; u < 2; u++) {
            size_t i = i0 + u * 256;
            float4 v = reinterpret_cast<const float4*>(x)[i];
            reinterpret_cast<__half2*>(g_xh)[2*i] =
                __half2(__float2half(v.x), __float2half(v.y));
            reinterpret_cast<__half2*>(g_xh)[2*i+1] =
                __half2(__float2half(v.z), __float2half(v.w));
        }
    }
}

// ---------------- gemm3: 128m x 192n (3 mats), 512 thr, warp 32m x 48n, BK=64 ----------------
#define ST3 ((128 + 192) * PAD64)       // 46080 B/stage
#define NKT3 (E_ / 64)                  // 32
#define FST 194                          // fp32 epilogue tile row stride (floats)
#define SM3 (3 * ST3)                    // 138240 B >= 128*194*4 = 99328 B
__global__ __launch_bounds__(512, 1) void gemm3_mma(const float* __restrict__ bg,
                                                    const float* __restrict__ bq) {
    extern __shared__ char sm[];
    uint32_t sb0 = smem_u32(sm);
    const int tid = threadIdx.x, wid = tid >> 5, lane = tid & 31;
    const int g = lane >> 2, t = lane & 3;
    const int wm = (wid & 3) * 32, wn = (wid >> 2) * 48;
    const int bn = blockIdx.x * 64, bm = blockIdx.y * 128;
    const int lrow = lane & 15;
    const int lcol = (lane >> 4) << 4;

    const __half* asrc = g_xh + (size_t)bm * E_;
    const __half* bsrc[3] = { g_wv + (size_t)bn * E_, g_wg + (size_t)bn * E_,
                              g_wq + (size_t)bn * E_ };

    float acc[2][6][4];
    #pragma unroll
    for (int i = 0; i < 2; i++)
        #pragma unroll
        for (int j = 0; j < 6; j++)
            #pragma unroll
            for (int e = 0; e < 4; e++) acc[i][j][e] = 0.f;

    auto load_stage = [&](int kt, int stg) {
        uint32_t sb = sb0 + stg * ST3;
        int k0 = kt * 64;
        #pragma unroll
        for (int j = 0; j < 5; j++) {                 // 2560 CP16
            int idx = tid + j * 512;
            if (idx < 1024) {                         // A: 128 rows x 8 chunks
                int r = idx >> 3, c = idx & 7;
                CP16(sb + r * PAD64 + c * 16, asrc + (size_t)r * E_ + k0 + c * 8);
            } else {                                  // B: 192 rows x 8 chunks
                int rem = idx - 1024;
                int r = rem >> 3, c = rem & 7;
                int mat = r >> 6, nrow = r & 63;
                CP16(sb + (128 + r) * PAD64 + c * 16,
                     bsrc[mat] + (size_t)nrow * E_ + k0 + c * 8);
            }
        }
    };

    load_stage(0, 0); CP_COMMIT();
    load_stage(1, 1); CP_COMMIT();
    CP_WAIT(1);
    __syncthreads();

    for (int kt = 0; kt < NKT3; kt++) {
        int stg = kt % 3;
        uint32_t sA = sb0 + stg * ST3;
        uint32_t sB = sA + 128 * PAD64;
        uint32_t aRow = sA + (wm + lrow) * PAD64 + lcol;
        uint32_t bRow = sB + (wn + lrow) * PAD64 + lcol;

        if (kt + 2 < NKT3) load_stage(kt + 2, (kt + 2) % 3);
        CP_COMMIT();

        #pragma unroll
        for (int ks = 0; ks < 4; ks++) {
            int co = ks * 32;
            uint32_t a[2][4];
            #pragma unroll
            for (int mb = 0; mb < 2; mb++)
                ldsm4(a[mb], aRow + mb * (16 * PAD64) + co);
            #pragma unroll
            for (int p = 0; p < 3; p++) {             // nb pairs {0,1},{2,3},{4,5}
                uint32_t br[4];
                ldsm4(br, bRow + p * (16 * PAD64) + co);
                uint32_t b0[2] = { br[0], br[2] };
                uint32_t b1[2] = { br[1], br[3] };
                #pragma unroll
                for (int mb = 0; mb < 2; mb++) {
                    mma16816(acc[mb][2 * p],     a[mb], b0);
                    mma16816(acc[mb][2 * p + 1], a[mb], b1);
                }
            }
        }
        CP_WAIT(1);
        __syncthreads();
    }

    // ---- fused epilogue: stage fp32 tile in smem, re-partition, gate,
    //      compute scan-tile carry (TS==128 aligns with bm tile),
    //      write packed half2 (store, que) ----
    float* sf = reinterpret_cast<float*>(sm);
    #pragma unroll
    for (int mb = 0; mb < 2; mb++)
        #pragma unroll
        for (int nb = 0; nb < 6; nb++) {
            int c192 = wn + nb * 8 + 2 * t;
            #pragma unroll
            for (int h = 0; h < 2; h++) {
                int r = wm + mb * 16 + g + h * 8;
                *reinterpret_cast<float2*>(&sf[r * FST + c192]) =
                    make_float2(acc[mb][nb][2 * h], acc[mb][nb][2 * h + 1]);
            }
        }
    __syncthreads();

    float pc;
    int c, m;
    {
        c = tid & 63;
        m = bn + c;
        float bgm = bg[m], bqm = bq[m];
        int r0 = tid >> 6;                            // 0..7
        float d8 = DECAY_F * DECAY_F;                 // d^2
        d8 = d8 * d8;                                 // d^4
        d8 = d8 * d8;                                 // d^8
        pc = 0.f;
        #pragma unroll 8
        for (int i = 0; i < 16; i++) {
            int r = r0 + i * 8;
            float v  = sf[r * FST + c];
            float gg = sf[r * FST + 64 + c];
            float qq = sf[r * FST + 128 + c];
            float s = v * sigf(gg + bgm) * SCALE_F;
            pc = fmaf(pc, d8, s);                     // sum s_r * d^(120-8i)
            float qv = sigf(qq + bqm) * SCALE_F;
            size_t row = (size_t)(bm + r);
            g_sq[row * M_ + m] = __floats2half2_rn(s, qv);
        }
        // exponent fix: need d^(127-r) = d^(127-r0-8i); have d^(120-8i) -> * d^(7-r0)
        #pragma unroll
        for (int k = 0; k < 7; k++)
            if (k < 7 - r0) pc *= DECAY_F;
    }
    __syncthreads();          // all tile reads done; reuse sf as scratch
    sf[tid] = pc;
    __syncthreads();
    if (tid < 64) {
        float tot = 0.f;
        #pragma unroll
        for (int k = 0; k < 8; k++) tot += sf[tid + 64 * k];
        int b  = bm >> 12;                   // bm / S_
        int jj = (bm & (S_ - 1)) >> 7;       // scan tile of 128 rows
        g_carry[((size_t)(b * NT + jj)) * M_ + m] = tot;
    }
}

// ---------------- gemm_out: 128m x 128n, warp 64m x 32n, 1-pass, BK=64, 2 CTA/SM ----------------
#define STO ((128 + 128) * PAD64)       // 36864 B/stage
#define NKTO (M_ / 64)                  // 32
__global__ __launch_bounds__(256, 2) void gemm_out_mma(float* __restrict__ out) {
    extern __shared__ char sm[];
    uint32_t sb0 = smem_u32(sm);
    const int tid = threadIdx.x, wid = tid >> 5, lane = tid & 31;
    const int g = lane >> 2, t = lane & 3;
    const int wm = (wid & 1) * 64, wn = (wid >> 1) * 32;
    const int bn = blockIdx.x * 128, bm = blockIdx.y * 128;
    const int lrow = lane & 15;
    const int lcol = (lane >> 4) << 4;

    const __half* asrc = g_ldh + (size_t)bm * M_;
    const __half* bsrc = g_wo + (size_t)bn * M_;

    float acc[4][4][4];
    #pragma unroll
    for (int i = 0; i < 4; i++)
        #pragma unroll
        for (int j = 0; j < 4; j++)
            #pragma unroll
            for (int e = 0; e < 4; e++) acc[i][j][e] = 0.f;

    auto load_stage = [&](int kt, int stg) {
        uint32_t sb = sb0 + stg * STO;
        int k0 = kt * 64;
        #pragma unroll
        for (int j = 0; j < 8; j++) {                 // 2048 CP16
            int idx = tid + j * 256;
            int half_ = idx >> 10, rem = idx & 1023, r = rem >> 3, c = rem & 7;
            const __half* src = half_ ? bsrc : asrc;
            CP16(sb + half_ * (128 * PAD64) + r * PAD64 + c * 16,
                 src + (size_t)r * M_ + k0 + c * 8);
        }
    };

    load_stage(0, 0); CP_COMMIT();

    for (int kt = 0; kt < NKTO; kt++) {
        if (kt + 1 < NKTO) {
            load_stage(kt + 1, (kt + 1) & 1);
            CP_COMMIT();
            CP_WAIT(1);
        } else {
            CP_WAIT(0);
        }
        __syncthreads();

        uint32_t sb = sb0 + (kt & 1) * STO;
        uint32_t aRow = sb + (wm + lrow) * PAD64 + lcol;
        uint32_t bRow = sb + 128 * PAD64 + (wn + lrow) * PAD64 + lcol;
        #pragma unroll
        for (int ks = 0; ks < 4; ks++) {
            int co = ks * 32;
            uint32_t a[4][4];
            #pragma unroll
            for (int mb = 0; mb < 4; mb++)
                ldsm4(a[mb], aRow + mb * (16 * PAD64) + co);
            #pragma unroll
            for (int p = 0; p < 2; p++) {
                uint32_t br[4];
                ldsm4(br, bRow + p * (16 * PAD64) + co);
                uint32_t b0[2] = { br[0], br[2] };
                uint32_t b1[2] = { br[1], br[3] };
                #pragma unroll
                for (int mb = 0; mb < 4; mb++) {
                    mma16816(acc[mb][2 * p],     a[mb], b0);
                    mma16816(acc[mb][2 * p + 1], a[mb], b1);
                }
            }
        }
        __syncthreads();
    }

    #pragma unroll
    for (int mb = 0; mb < 4; mb++)
        #pragma unroll
        for (int nb = 0; nb < 4; nb++) {
            int col = bn + wn + nb * 8 + 2 * t;
            #pragma unroll
            for (int h = 0; h < 2; h++) {
                size_t row = (size_t)(bm + wm + mb * 16 + g + h * 8);
                *reinterpret_cast<float2*>(&out[row * E_ + col]) =
                    make_float2(acc[mb][nb][2 * h], acc[mb][nb][2 * h + 1]);
            }
        }
}

// ---------------- apply (prefix fused in; carry from gemm3) ----------------
__global__ __launch_bounds__(128) void apply_kernel() {
    int m = blockIdx.x * 128 + threadIdx.x;
    int j = blockIdx.y, b = blockIdx.z;
    // inline prefix: run over carries 0..j-1 (identical order to old prefix_kernel)
    float aTS = DECAY_F;
    #pragma unroll
    for (int i = 0; i < 7; i++) aTS *= aTS;          // 0.95^128
    float c = 0.f;
    for (int j2 = 0; j2 < j; j2++)
        c = g_carry[(size_t)(b * NT + j2) * M_ + m] + aTS * c;

    size_t base = ((size_t)(b * S_ + j * TS)) * M_ + m;
    #pragma unroll 8
    for (int t = 0; t < TS; t++) {
        size_t idx = base + (size_t)t * M_;
        float2 f = __half22float2(g_sq[idx]);
        c = fmaf(DECAY_F, c, f.x);
        g_ldh[idx] = __float2half(c * f.y);
    }
}

// ---------------- launch ----------------
extern "C" void kernel_launch(void* const* d_in, const int* in_sizes, int n_in,
                              void* d_out, int out_size) {
    const float* x  = (const float*)d_in[0];
    const float* Wv = (const float*)d_in[1];
    const float* Wg = (const float*)d_in[2];
    const float* bg = (const float*)d_in[3];
    const float* Wq = (const float*)d_in[4];
    const float* bq = (const float*)d_in[5];
    const float* Wo = (const float*)d_in[6];
    float* out = (float*)d_out;

    cudaFuncSetAttribute(gemm3_mma, cudaFuncAttributeMaxDynamicSharedMemorySize, SM3);
    cudaFuncSetAttribute(gemm_out_mma, cudaFuncAttributeMaxDynamicSharedMemorySize, 2 * STO);

    __half *wv, *wg, *wq, *wo;
    cudaGetSymbolAddress((void**)&wv, g_wv);
    cudaGetSymbolAddress((void**)&wg, g_wg);
    cudaGetSymbolAddress((void**)&wq, g_wq);
    cudaGetSymbolAddress((void**)&wo, g_wo);

    int nx = ((size_t)N1 * E_ / 4) / 512;            // 16384 split_x blocks
    prep_kernel<<<NPREP_W + nx, 256>>>(x, Wv, Wg, Wq, Wo, wv, wg, wq, wo);

    gemm3_mma<<<dim3(M_ / 64, N1 / 128), 512, SM3>>>(bg, bq);

    dim3 gscan(M_ / 128, NT, B_);
    apply_kernel<<<gscan, 128>>>();

    gemm_out_mma<<<dim3(E_ / 128, N1 / 128), 256, 2 * STO>>>(out);
}